// round 12
// baseline (speedup 1.0000x reference)
#include <cuda_runtime.h>
#include <cuda_fp16.h>
#include <math.h>

#define NN 4096
#define NV 3
#define MMDIM 16
#define EE 256
#define HH 8
#define DD 32
#define ROWS (NN*NV)

__device__ float scratch[26607616];

// word offsets
#define OFF_GRAM    0u          // h16 [4096,1024]
#define OFF_HID     2097152u    // h16 [4096,512]
#define OFF_H2HI    3145728u    // h16 [4096,512]
#define OFF_H2LO    4194304u
#define OFF_QHI     5242880u    // h16 [4096,256]
#define OFF_QLO     5767168u
#define OFF_KHI     6291456u
#define OFF_KLO     6815744u
#define OFF_VPAIR   9437184u    // half2 [2048][8][128]
#define OFF_OUTV    11534336u   // h16 [4096,256]
#define OFF_OUTG    12058624u   // h16 [12288,256]
#define OFF_HPRE    13631488u   // f32 [4096,256]
#define OFF_PG1     14680064u
#define OFF_PG2     14942208u
#define OFF_PQH     15007744u
#define OFF_PQL     15073280u
#define OFF_PKH     15138816u
#define OFF_PKL     15204352u
#define OFF_PV      15269888u
#define OFF_PHDH    15335424u
#define OFF_PHDL    15368192u
#define OFF_W3P     15400960u
#define OFF_WG      15433728u
#define OFF_W1      15434240u
#define OFF_WVG2    15434496u
#define OFF_W2F     15438592u
#define OFF_BIAS2   15442688u

// ---------------------------------------------------------------------------
// helpers
// ---------------------------------------------------------------------------
__device__ __forceinline__ void mma_f16(float c[4],
                                        unsigned a0, unsigned a1, unsigned a2, unsigned a3,
                                        unsigned b0, unsigned b1) {
    asm volatile(
        "mma.sync.aligned.m16n8k16.row.col.f32.f16.f16.f32 "
        "{%0,%1,%2,%3}, {%4,%5,%6,%7}, {%8,%9}, {%0,%1,%2,%3};"
        : "+f"(c[0]), "+f"(c[1]), "+f"(c[2]), "+f"(c[3])
        : "r"(a0), "r"(a1), "r"(a2), "r"(a3), "r"(b0), "r"(b1));
}

__device__ __forceinline__ unsigned h2pack(float a, float b) {
    __half2 h = __floats2half2_rn(a, b);
    return *(unsigned*)&h;
}

__device__ __forceinline__ void cp_async16(void* smem, const void* gmem) {
    unsigned s = (unsigned)__cvta_generic_to_shared(smem);
    asm volatile("cp.async.cg.shared.global [%0], [%1], 16;" :: "r"(s), "l"(gmem));
}
#define CP_COMMIT() asm volatile("cp.async.commit_group;")
#define CP_WAIT(n)  asm volatile("cp.async.wait_group %0;" :: "n"(n))

// ---------------------------------------------------------------------------
// Weight packing (half2 kp-pairs)
// ---------------------------------------------------------------------------
__device__ __forceinline__ void pack_one(const float* __restrict__ W, int N, int i,
                                         unsigned* __restrict__ H, unsigned* __restrict__ L)
{
    int kp = i / N, n = i - kp * N;
    float x0 = W[(size_t)(2 * kp) * N + n];
    float x1 = W[(size_t)(2 * kp + 1) * N + n];
    __half h0 = __float2half_rn(x0), h1 = __float2half_rn(x1);
    __half2 hh = __halves2half2(h0, h1);
    H[i] = *(unsigned*)&hh;
    if (L) {
        __half2 ll = __floats2half2_rn(x0 - __half2float(h0), x1 - __half2float(h1));
        L[i] = *(unsigned*)&ll;
    }
}

__global__ void pack_weights(const float* Wg1, const float* Wg2, const float* Wq,
                             const float* Wk, const float* Wv, const float* Whd,
                             unsigned* Pg1, unsigned* Pg2,
                             unsigned* Pqh, unsigned* Pql,
                             unsigned* Pkh, unsigned* Pkl,
                             unsigned* Pv, unsigned* Phdh, unsigned* Phdl)
{
    int idx = blockIdx.x * 256 + threadIdx.x;
    if (idx < 262144) { pack_one(Wg1, 512, idx, Pg1, nullptr); return; }
    idx -= 262144;
    if (idx < 65536) { pack_one(Wg2, 256, idx, Pg2, nullptr); return; }
    idx -= 65536;
    if (idx < 65536) { pack_one(Wq, 256, idx, Pqh, Pql); return; }
    idx -= 65536;
    if (idx < 65536) { pack_one(Wk, 256, idx, Pkh, Pkl); return; }
    idx -= 65536;
    if (idx < 65536) { pack_one(Wv, 256, idx, Pv, nullptr); return; }
    idx -= 65536;
    if (idx < 32768) { pack_one(Whd, 256, idx, Phdh, Phdl); return; }
}

// ---------------------------------------------------------------------------
// Prep: small weight combinations (fp32)
// ---------------------------------------------------------------------------
__global__ void prep_small(const float* __restrict__ We, const float* __restrict__ Wgp,
                           const float* __restrict__ Wgd, const float* __restrict__ Wvg,
                           const float* __restrict__ Wgo,
                           float* Wg, float* W1, float* Wvg2, float* W2f)
{
    int idx = blockIdx.x * 256 + threadIdx.x;
    if (idx < 512) {
        int m = idx >> 5, n = idx & 31;
        float a = 0;
        for (int e = 0; e < 256; e++) a += We[m * 256 + e] * Wgp[e * 32 + n];
        Wg[idx] = 16.f * a; return;
    }
    idx -= 512;
    if (idx < 256) {
        int m = idx >> 4, j = idx & 15;
        float a = 0;
        for (int e = 0; e < 256; e++) a += We[m * 256 + e] * Wgd[e * 16 + j];
        W1[idx] = 16.f * a; return;
    }
    idx -= 256;
    if (idx < 4096) {
        int m = idx >> 8, c = idx & 255;
        float a = 0;
        for (int e = 0; e < 256; e++) a += We[m * 256 + e] * Wvg[e * 256 + c];
        Wvg2[idx] = 16.f * a; return;
    }
    idx -= 4096;
    if (idx < 4096) {
        int k = idx >> 4, j = idx & 15;
        float a = 0;
        for (int e = 0; e < 256; e++) a += Wgo[k * 256 + e] * Wgd[e * 16 + j];
        W2f[idx] = a;
    }
}

// W3p = pack(W_ng @ W_hdec); bias2 = b_ng@W_hdec + b_hdec
__global__ void prep_w3(const float* __restrict__ Wng, const float* __restrict__ Whd,
                        const float* __restrict__ bng, const float* __restrict__ bhd,
                        unsigned* W3p, float* bias2)
{
    int idx = blockIdx.x * 256 + threadIdx.x;
    if (idx < 32768) {
        int kp = idx >> 8, n = idx & 255;
        float a0 = 0, a1 = 0;
        for (int e = 0; e < 256; e++) {
            float w = Whd[e * 256 + n];
            a0 += Wng[(2 * kp) * 256 + e] * w;
            a1 += Wng[(2 * kp + 1) * 256 + e] * w;
        }
        __half2 h = __floats2half2_rn(a0, a1);
        W3p[idx] = *(unsigned*)&h;
        return;
    }
    idx -= 32768;
    if (idx < 256) {
        float a = bhd[idx];
        for (int k = 0; k < 256; k++) a += bng[k] * Whd[k * 256 + idx];
        bias2[idx] = a;
    }
}

// ---------------------------------------------------------------------------
// Fused g2p + gram
// ---------------------------------------------------------------------------
__global__ __launch_bounds__(128)
void g2p_gram(const float* __restrict__ equ, const float* __restrict__ Wg,
              __half* __restrict__ gram)
{
    __shared__ float wgs[512];
    __shared__ float es[48];
    __shared__ float g2s[96];
    int t = threadIdx.x;
    int node = blockIdx.x;
    #pragma unroll
    for (int i = 0; i < 4; i++) wgs[t + i * 128] = Wg[t + i * 128];
    if (t < 48) es[t] = equ[(size_t)node * 48 + t];
    __syncthreads();
    if (t < 96) {
        int i = t >> 5, a = t & 31;
        float acc = 0;
        #pragma unroll
        for (int k = 0; k < 16; k++) acc += es[i * 16 + k] * wgs[k * 32 + a];
        g2s[t] = acc;
    }
    __syncthreads();
    #pragma unroll
    for (int o = t; o < 1024; o += 128) {
        int a = o >> 5, b = o & 31;
        gram[(size_t)node * 1024 + o] = __float2half_rn(
            g2s[a] * g2s[b] + g2s[32 + a] * g2s[32 + b] + g2s[64 + a] * g2s[64 + b]);
    }
}

// vg = equ @ Wvg2 (K=16), written directly into paired attention layout.
__global__ __launch_bounds__(256)
void vg_small(const float* __restrict__ equ, const float* __restrict__ Wvg2,
              __half* __restrict__ vpH)
{
    __shared__ float ws[16 * 256];
    __shared__ float es[64 * 16];
    int tid = threadIdx.x;
    #pragma unroll
    for (int i = 0; i < 16; i++) ws[tid + i * 256] = Wvg2[tid + i * 256];
    int r0 = blockIdx.x * 64;
    #pragma unroll
    for (int i = 0; i < 4; i++) {
        int idx = tid + i * 256;
        es[idx] = equ[(size_t)r0 * 16 + idx];
    }
    __syncthreads();
    const int head = tid >> 5, d = tid & 31;
    for (int r = 0; r < 64; r++) {
        float acc = 0;
        #pragma unroll
        for (int k = 0; k < 16; k++) acc += es[r * 16 + k] * ws[k * 256 + tid];
        int gr = r0 + r;
        int node = gr / 3;
        int ch = gr - 3 * node;
        size_t w = ((size_t)(node >> 1) * 1024 + head * 128 + 32 + ch * 32 + d) * 2 + (node & 1);
        vpH[w] = __float2half_rn(acc);
    }
}

// h2 right half = 16h split hi/lo
__global__ void h2fill_kernel(const float* __restrict__ h,
                              __half* __restrict__ h2hi, __half* __restrict__ h2lo)
{
    int idx = blockIdx.x * blockDim.x + threadIdx.x;
    if (idx < NN * EE) {
        int r = idx >> 8, c = idx & 255;
        float v = 16.f * h[idx];
        __half hi = __float2half_rn(v);
        size_t o = (size_t)r * 512 + 256 + c;
        h2hi[o] = hi;
        h2lo[o] = __float2half_rn(v - __half2float(hi));
    }
}

// equ_out = equ@W1 + outg@W2f  (N=16 fused)
__global__ __launch_bounds__(256)
void equ_out_kernel(const float* __restrict__ equ, const __half* __restrict__ outg,
                    const float* __restrict__ W1, const float* __restrict__ W2,
                    float* __restrict__ out)
{
    __shared__ float w1s[256];
    __shared__ float w2s[4096];
    int tid = threadIdx.x;
    w1s[tid] = W1[tid];
    #pragma unroll
    for (int i = 0; i < 16; i++) w2s[tid + i * 256] = W2[tid + i * 256];
    __syncthreads();
    int lane = tid & 31, warp = tid >> 5;
    int row = blockIdx.x * 16 + warp * 2 + (lane >> 4);
    int j = lane & 15;
    float acc = 0;
    const float* er = equ + (size_t)row * 16;
    #pragma unroll
    for (int k = 0; k < 16; k++) acc += er[k] * w1s[k * 16 + j];
    const __half2* og = (const __half2*)(outg + (size_t)row * 256);
    #pragma unroll 8
    for (int kp = 0; kp < 128; kp++) {
        float2 v = __half22float2(og[kp]);
        acc += v.x * w2s[(2 * kp) * 16 + j] + v.y * w2s[(2 * kp + 1) * 16 + j];
    }
    out[(size_t)row * 16 + j] = acc;
}

// ---------------------------------------------------------------------------
// FP16 GEMM, 64x128 tile (8 warps, warp tile 32x32), 3-stage cp.async pipeline.
// (round-8 configuration: best measured aggregate)
// ---------------------------------------------------------------------------
#define HA_STR 20
#define HB_STR 136
#define ASZ (64*HA_STR)
#define BSZ (16*HB_STR)

__device__ __forceinline__ void epi_store(float v0, float v1,
                                          float* outF, __half* outH, __half* outL,
                                          size_t off)
{
    if (outF) {
        *(float2*)&outF[off] = make_float2(v0, v1);
    } else if (outL) {
        __half h0 = __float2half_rn(v0), h1 = __float2half_rn(v1);
        __half2 hh = __halves2half2(h0, h1);
        ((__half2*)outH)[off >> 1] = hh;
        ((__half2*)outL)[off >> 1] =
            __floats2half2_rn(v0 - __half2float(h0), v1 - __half2float(h1));
    } else {
        ((__half2*)outH)[off >> 1] = __floats2half2_rn(v0, v1);
    }
}

#define STAGE_A_G(SRC, DST, K0) { \
    int row_ = tid >> 2, seg_ = tid & 3; \
    cp_async16(&(DST)[row_ * HA_STR + seg_ * 4], \
               &(SRC)[(size_t)(bm + row_) * lda + (K0) + seg_ * 8]); }
#define STAGE_B_G(SRC, DST, K0) { \
    _Pragma("unroll") \
    for (int i = 0; i < 2; i++) { \
        int idx = tid + i * 256; \
        int kp = idx >> 5, s = idx & 31; \
        cp_async16(&(DST)[kp * HB_STR + s * 4], \
                   &(SRC)[(size_t)(((K0) >> 1) + kp) * ldbw + bn + s * 4]); \
    } }

template<int NPASS, bool RELU>
__global__ __launch_bounds__(256)
void hgemm(const __half* __restrict__ A, const __half* __restrict__ Al, int lda,
           const unsigned* __restrict__ Bp, const unsigned* __restrict__ Bl, int ldbw,
           const float* __restrict__ bias,
           const float* __restrict__ Res, int ldres, float resScale, float alpha,
           float* __restrict__ outF, __half* __restrict__ outH, __half* __restrict__ outL,
           int ldc, int K)
{
    extern __shared__ unsigned smw[];
    unsigned* As  = smw;                 // 3 stages
    unsigned* Bs  = smw + 3 * ASZ;
    unsigned* Als = Bs + 3 * BSZ;
    unsigned* Bls = Als + 3 * ASZ;

    const int tid  = threadIdx.x;
    const int lane = tid & 31;
    const int warp = tid >> 5;
    const int bm   = blockIdx.y * 64;
    const int bn   = blockIdx.x * 128;
    const int wM   = (warp >> 2) * 32;
    const int wN   = (warp & 3) * 32;
    const int lr   = lane >> 2;
    const int lc   = lane & 3;

    float acc[2][4][4] = {};
    const int KT = K / 32;   // >= 3

    STAGE_A_G(A, As, 0);
    if (NPASS == 3) STAGE_A_G(Al, Als, 0);
    STAGE_B_G(Bp, Bs, 0);
    if (NPASS == 3) STAGE_B_G(Bl, Bls, 0);
    CP_COMMIT();
    STAGE_A_G(A, As + ASZ, 32);
    if (NPASS == 3) STAGE_A_G(Al, Als + ASZ, 32);
    STAGE_B_G(Bp, Bs + BSZ, 32);
    if (NPASS == 3) STAGE_B_G(Bl, Bls + BSZ, 32);
    CP_COMMIT();

    int scur = 0;
    for (int kt = 0; kt < KT; kt++) {
        if (kt + 2 < KT) {
            int s2 = scur + 2; if (s2 >= 3) s2 -= 3;
            int k0 = (kt + 2) * 32;
            STAGE_A_G(A, As + s2 * ASZ, k0);
            if (NPASS == 3) STAGE_A_G(Al, Als + s2 * ASZ, k0);
            STAGE_B_G(Bp, Bs + s2 * BSZ, k0);
            if (NPASS == 3) STAGE_B_G(Bl, Bls + s2 * BSZ, k0);
            CP_COMMIT();
            CP_WAIT(2);
        } else if (kt + 1 < KT) {
            CP_WAIT(1);
        } else {
            CP_WAIT(0);
        }
        __syncthreads();

        const unsigned* Ac  = As  + scur * ASZ;
        const unsigned* Bc  = Bs  + scur * BSZ;
        const unsigned* Alc = Als + scur * ASZ;
        const unsigned* Blc = Bls + scur * BSZ;

        #pragma unroll
        for (int ks = 0; ks < 2; ks++) {
            unsigned ah[2][4], al[2][4];
            #pragma unroll
            for (int mt = 0; mt < 2; mt++) {
                int rb = wM + mt * 16 + lr;
                int c  = ks * 8 + lc;
                ah[mt][0] = Ac[rb * HA_STR + c];
                ah[mt][1] = Ac[(rb + 8) * HA_STR + c];
                ah[mt][2] = Ac[rb * HA_STR + c + 4];
                ah[mt][3] = Ac[(rb + 8) * HA_STR + c + 4];
                if (NPASS == 3) {
                    al[mt][0] = Alc[rb * HA_STR + c];
                    al[mt][1] = Alc[(rb + 8) * HA_STR + c];
                    al[mt][2] = Alc[rb * HA_STR + c + 4];
                    al[mt][3] = Alc[(rb + 8) * HA_STR + c + 4];
                }
            }
            unsigned bh[4][2], bl[4][2];
            #pragma unroll
            for (int nt = 0; nt < 4; nt++) {
                int n  = wN + nt * 8 + lr;
                int kp = ks * 8 + lc;
                bh[nt][0] = Bc[kp * HB_STR + n];
                bh[nt][1] = Bc[(kp + 4) * HB_STR + n];
                if (NPASS == 3) {
                    bl[nt][0] = Blc[kp * HB_STR + n];
                    bl[nt][1] = Blc[(kp + 4) * HB_STR + n];
                }
            }
            #pragma unroll
            for (int mt = 0; mt < 2; mt++)
                #pragma unroll
                for (int nt = 0; nt < 4; nt++) {
                    mma_f16(acc[mt][nt], ah[mt][0], ah[mt][1], ah[mt][2], ah[mt][3],
                            bh[nt][0], bh[nt][1]);
                    if (NPASS == 3) {
                        mma_f16(acc[mt][nt], ah[mt][0], ah[mt][1], ah[mt][2], ah[mt][3],
                                bl[nt][0], bl[nt][1]);
                        mma_f16(acc[mt][nt], al[mt][0], al[mt][1], al[mt][2], al[mt][3],
                                bh[nt][0], bh[nt][1]);
                    }
                }
        }
        __syncthreads();
        scur = scur + 1; if (scur == 3) scur = 0;
    }

    #pragma unroll
    for (int mt = 0; mt < 2; mt++) {
        #pragma unroll
        for (int nt = 0; nt < 4; nt++) {
            int col = bn + wN + nt * 8 + 2 * lc;
            #pragma unroll
            for (int half = 0; half < 2; half++) {
                int r = bm + wM + mt * 16 + lr + half * 8;
                float v0 = acc[mt][nt][half * 2 + 0];
                float v1 = acc[mt][nt][half * 2 + 1];
                if (bias) { v0 += bias[col]; v1 += bias[col + 1]; }
                v0 *= alpha; v1 *= alpha;
                if (Res) {
                    v0 = fmaf(resScale, Res[(size_t)r * ldres + col], v0);
                    v1 = fmaf(resScale, Res[(size_t)r * ldres + col + 1], v1);
                }
                if (RELU) { v0 = fmaxf(v0, 0.f); v1 = fmaxf(v1, 0.f); }
                epi_store(v0, v1, outF, outH, outL, (size_t)r * ldc + col);
            }
        }
    }
}

// ---------------------------------------------------------------------------
// Fused QKV (q/k x3 split-out; v x1 direct to vpair layout). 64x128 tiles.
// ---------------------------------------------------------------------------
__global__ __launch_bounds__(256)
void qkv_hgemm(const __half* __restrict__ A, const __half* __restrict__ Al,
               const unsigned* __restrict__ Pqh, const unsigned* __restrict__ Pql,
               const unsigned* __restrict__ Pkh, const unsigned* __restrict__ Pkl,
               const unsigned* __restrict__ Pv,
               const float* __restrict__ bq, const float* __restrict__ bk,
               const float* __restrict__ bv,
               __half* qh, __half* ql, __half* kh, __half* kl,
               __half* __restrict__ vpH,
               float qalpha)
{
    extern __shared__ unsigned smw[];
    unsigned* As  = smw;
    unsigned* Bs  = smw + 3 * ASZ;
    unsigned* Als = Bs + 3 * BSZ;
    unsigned* Bls = Als + 3 * ASZ;

    const int seg = blockIdx.z;
    const bool x3 = (seg < 2);
    const unsigned* Bp = (seg == 0) ? Pqh : (seg == 1) ? Pkh : Pv;
    const unsigned* Bl = (seg == 0) ? Pql : (seg == 1) ? Pkl : nullptr;
    const float* bias  = (seg == 0) ? bq : (seg == 1) ? bk : bv;
    __half* outH = (seg == 0) ? qh : kh;
    __half* outL = (seg == 0) ? ql : kl;
    const float alpha = (seg == 0) ? qalpha : 1.f;
    const int lda = 512, ldbw = 256, ldc = 256, K = 512;

    const int tid  = threadIdx.x;
    const int lane = tid & 31;
    const int warp = tid >> 5;
    const int bm   = blockIdx.y * 64;
    const int bn   = blockIdx.x * 128;
    const int wM   = (warp >> 2) * 32;
    const int wN   = (warp & 3) * 32;
    const int lr   = lane >> 2;
    const int lc   = lane & 3;

    float acc[2][4][4] = {};
    const int KT = K / 32;   // 16

    STAGE_A_G(A, As, 0);
    if (x3) STAGE_A_G(Al, Als, 0);
    STAGE_B_G(Bp, Bs, 0);
    if (x3) STAGE_B_G(Bl, Bls, 0);
    CP_COMMIT();
    STAGE_A_G(A, As + ASZ, 32);
    if (x3) STAGE_A_G(Al, Als + ASZ, 32);
    STAGE_B_G(Bp, Bs + BSZ, 32);
    if (x3) STAGE_B_G(Bl, Bls + BSZ, 32);
    CP_COMMIT();

    int scur = 0;
    for (int kt = 0; kt < KT; kt++) {
        if (kt + 2 < KT) {
            int s2 = scur + 2; if (s2 >= 3) s2 -= 3;
            int k0 = (kt + 2) * 32;
            STAGE_A_G(A, As + s2 * ASZ, k0);
            if (x3) STAGE_A_G(Al, Als + s2 * ASZ, k0);
            STAGE_B_G(Bp, Bs + s2 * BSZ, k0);
            if (x3) STAGE_B_G(Bl, Bls + s2 * BSZ, k0);
            CP_COMMIT();
            CP_WAIT(2);
        } else if (kt + 1 < KT) {
            CP_WAIT(1);
        } else {
            CP_WAIT(0);
        }
        __syncthreads();

        const unsigned* Ac  = As  + scur * ASZ;
        const unsigned* Bc  = Bs  + scur * BSZ;
        const unsigned* Alc = Als + scur * ASZ;
        const unsigned* Blc = Bls + scur * BSZ;

        #pragma unroll
        for (int ks = 0; ks < 2; ks++) {
            unsigned ah[2][4], al[2][4];
            #pragma unroll
            for (int mt = 0; mt < 2; mt++) {
                int rb = wM + mt * 16 + lr;
                int c  = ks * 8 + lc;
                ah[mt][0] = Ac[rb * HA_STR + c];
                ah[mt][1] = Ac[(rb + 8) * HA_STR + c];
                ah[mt][2] = Ac[rb * HA_STR + c + 4];
                ah[mt][3] = Ac[(rb + 8) * HA_STR + c + 4];
                if (x3) {
                    al[mt][0] = Alc[rb * HA_STR + c];
                    al[mt][1] = Alc[(rb + 8) * HA_STR + c];
                    al[mt][2] = Alc[rb * HA_STR + c + 4];
                    al[mt][3] = Alc[(rb + 8) * HA_STR + c + 4];
                }
            }
            unsigned bh[4][2], bl[4][2];
            #pragma unroll
            for (int nt = 0; nt < 4; nt++) {
                int n  = wN + nt * 8 + lr;
                int kp = ks * 8 + lc;
                bh[nt][0] = Bc[kp * HB_STR + n];
                bh[nt][1] = Bc[(kp + 4) * HB_STR + n];
                if (x3) {
                    bl[nt][0] = Blc[kp * HB_STR + n];
                    bl[nt][1] = Blc[(kp + 4) * HB_STR + n];
                }
            }
            #pragma unroll
            for (int mt = 0; mt < 2; mt++)
                #pragma unroll
                for (int nt = 0; nt < 4; nt++) {
                    mma_f16(acc[mt][nt], ah[mt][0], ah[mt][1], ah[mt][2], ah[mt][3],
                            bh[nt][0], bh[nt][1]);
                    if (x3) {
                        mma_f16(acc[mt][nt], ah[mt][0], ah[mt][1], ah[mt][2], ah[mt][3],
                                bl[nt][0], bl[nt][1]);
                        mma_f16(acc[mt][nt], al[mt][0], al[mt][1], al[mt][2], al[mt][3],
                                bh[nt][0], bh[nt][1]);
                    }
                }
        }
        __syncthreads();
        scur = scur + 1; if (scur == 3) scur = 0;
    }

    #pragma unroll
    for (int mt = 0; mt < 2; mt++) {
        #pragma unroll
        for (int nt = 0; nt < 4; nt++) {
            int col = bn + wN + nt * 8 + 2 * lc;
            #pragma unroll
            for (int half = 0; half < 2; half++) {
                int r = bm + wM + mt * 16 + lr + half * 8;
                float v0 = (acc[mt][nt][half * 2 + 0] + bias[col]) * alpha;
                float v1 = (acc[mt][nt][half * 2 + 1] + bias[col + 1]) * alpha;
                if (seg == 2) {
                    int head = col >> 5, d = col & 31;
                    size_t w = ((size_t)(r >> 1) * 1024 + head * 128 + d) * 2 + (r & 1);
                    vpH[w]     = __float2half_rn(v0);
                    vpH[w + 2] = __float2half_rn(v1);
                } else {
                    epi_store(v0, v1, nullptr, outH, outL, (size_t)r * ldc + col);
                }
            }
        }
    }
}

// ---------------------------------------------------------------------------
// Flash attention v9: triple-buffered K/V rings, one sync/tile, exp2 softmax,
// warp-voted O-rescale skip (alpha==1 on most tiles after warmup).
// ---------------------------------------------------------------------------
#define AQ 128
#define AK 64
#define QP 20
#define VPSTR 136
#define KBUF 1280
#define VBUF 4352

#define ATTN_WORDS (2560*2 + 3*KBUF*2 + 3*VBUF)   // 25856
#define ATTN_SMEM  (ATTN_WORDS * 4)               // 103424

__global__ __launch_bounds__(256, 2)
void attn_kernel(const unsigned* __restrict__ qhiW, const unsigned* __restrict__ qloW,
                 const unsigned* __restrict__ khiW, const unsigned* __restrict__ kloW,
                 const unsigned* __restrict__ vpW,
                 __half* __restrict__ outv, __half* __restrict__ outg)
{
    extern __shared__ unsigned smw[];
    unsigned* Qhi  = smw;                    // [128][QP]
    unsigned* Qlo  = Qhi + 2560;
    unsigned* Khi3 = Qlo + 2560;             // 3 x [64][QP]
    unsigned* Klo3 = Khi3 + 3 * KBUF;
    unsigned* Vp3  = Klo3 + 3 * KBUF;        // 3 x [32][VPSTR]

    const int head = blockIdx.y;
    const int qb   = blockIdx.x * AQ;
    const int tid  = threadIdx.x;
    const int lane = tid & 31;
    const int warp = tid >> 5;
    const int hofw = head * 16;
    const int hof  = head * DD;
    const int lr   = lane >> 2;
    const int lc   = lane & 3;
    const int wRow = warp * 16;

    // prologue: V(0) group, then K(0)+Q group
    {
        #pragma unroll
        for (int i = 0; i < 4; i++) {
            int idx = tid + i * 256;
            int pr = idx >> 5, s = idx & 31;
            cp_async16(&Vp3[pr * VPSTR + s * 4],
                       &vpW[(size_t)pr * 1024 + head * 128 + s * 4]);
        }
        CP_COMMIT();
    }
    {
        int key = tid >> 2, seg = tid & 3;
        cp_async16(&Khi3[key * QP + seg * 4], &khiW[(size_t)key * 128 + hofw + seg * 4]);
        cp_async16(&Klo3[key * QP + seg * 4], &kloW[(size_t)key * 128 + hofw + seg * 4]);
        #pragma unroll
        for (int i = 0; i < 2; i++) {
            int idx = tid + i * 256;
            int row = idx >> 2, sg = idx & 3;
            cp_async16(&Qhi[row * QP + sg * 4], &qhiW[(size_t)(qb + row) * 128 + hofw + sg * 4]);
            cp_async16(&Qlo[row * QP + sg * 4], &qloW[(size_t)(qb + row) * 128 + hofw + sg * 4]);
        }
        CP_COMMIT();
    }

    float O[16][4] = {};
    float m0 = -1e30f, m1 = -1e30f, l0 = 0.f, l1 = 0.f;

    int bcur = 0;
    for (int t = 0; t < NN / AK; t++) {
        const bool hasNext = (t + 1 < NN / AK);
        int bnext = bcur + 1; if (bnext == 3) bnext = 0;

        if (hasNext) {
            const int kb1 = (t + 1) * AK;
            unsigned* Vd = Vp3 + bnext * VBUF;
            const int p0 = kb1 >> 1;
            #pragma unroll
            for (int i = 0; i < 4; i++) {
                int idx = tid + i * 256;
                int pr = idx >> 5, s = idx & 31;
                cp_async16(&Vd[pr * VPSTR + s * 4],
                           &vpW[((size_t)(p0 + pr)) * 1024 + head * 128 + s * 4]);
            }
            CP_COMMIT();
            unsigned* Kdh = Khi3 + bnext * KBUF;
            unsigned* Kdl = Klo3 + bnext * KBUF;
            int key = tid >> 2, seg = tid & 3;
            cp_async16(&Kdh[key * QP + seg * 4],
                       &khiW[(size_t)(kb1 + key) * 128 + hofw + seg * 4]);
            cp_async16(&Kdl[key * QP + seg * 4],
                       &kloW[(size_t)(kb1 + key) * 128 + hofw + seg * 4]);
            CP_COMMIT();
            CP_WAIT(2);
        } else {
            CP_WAIT(0);
        }
        __syncthreads();

        const unsigned* Kh = Khi3 + bcur * KBUF;
        const unsigned* Kl = Klo3 + bcur * KBUF;
        const unsigned* Vp = Vp3 + bcur * VBUF;

        #pragma unroll
        for (int half = 0; half < 2; half++) {
            // ---- S = Q K^T (fp16x3) ----
            float s[4][4] = {};
            #pragma unroll
            for (int ks = 0; ks < 2; ks++) {
                int rb = wRow + lr;
                int c  = ks * 8 + lc;
                unsigned ah0 = Qhi[rb * QP + c],     ah1 = Qhi[(rb + 8) * QP + c];
                unsigned ah2 = Qhi[rb * QP + c + 4], ah3 = Qhi[(rb + 8) * QP + c + 4];
                unsigned al0 = Qlo[rb * QP + c],     al1 = Qlo[(rb + 8) * QP + c];
                unsigned al2 = Qlo[rb * QP + c + 4], al3 = Qlo[(rb + 8) * QP + c + 4];
                #pragma unroll
                for (int nt = 0; nt < 4; nt++) {
                    int key = half * 32 + nt * 8 + lr;
                    unsigned bh0 = Kh[key * QP + c];
                    unsigned bh1 = Kh[key * QP + c + 4];
                    unsigned bl0 = Kl[key * QP + c];
                    unsigned bl1 = Kl[key * QP + c + 4];
                    mma_f16(s[nt], ah0, ah1, ah2, ah3, bh0, bh1);
                    mma_f16(s[nt], ah0, ah1, ah2, ah3, bl0, bl1);
                    mma_f16(s[nt], al0, al1, al2, al3, bh0, bh1);
                }
            }

            // ---- online softmax (base 2; q pre-scaled by log2 e) ----
            float mx0 = m0, mx1 = m1;
            #pragma unroll
            for (int nt = 0; nt < 4; nt++) {
                mx0 = fmaxf(mx0, fmaxf(s[nt][0], s[nt][1]));
                mx1 = fmaxf(mx1, fmaxf(s[nt][2], s[nt][3]));
            }
            mx0 = fmaxf(mx0, __shfl_xor_sync(0xffffffff, mx0, 1));
            mx0 = fmaxf(mx0, __shfl_xor_sync(0xffffffff, mx0, 2));
            mx1 = fmaxf(mx1, __shfl_xor_sync(0xffffffff, mx1, 1));
            mx1 = fmaxf(mx1, __shfl_xor_sync(0xffffffff, mx1, 2));

            float alpha0 = exp2f(m0 - mx0);
            float alpha1 = exp2f(m1 - mx1);
            float sum0 = 0.f, sum1 = 0.f;
            #pragma unroll
            for (int nt = 0; nt < 4; nt++) {
                s[nt][0] = exp2f(s[nt][0] - mx0);
                s[nt][1] = exp2f(s[nt][1] - mx0);
                s[nt][2] = exp2f(s[nt][2] - mx1);
                s[nt][3] = exp2f(s[nt][3] - mx1);
                sum0 += s[nt][0] + s[nt][1];
                sum1 += s[nt][2] + s[nt][3];
            }
            sum0 += __shfl_xor_sync(0xffffffff, sum0, 1);
            sum0 += __shfl_xor_sync(0xffffffff, sum0, 2);
            sum1 += __shfl_xor_sync(0xffffffff, sum1, 1);
            sum1 += __shfl_xor_sync(0xffffffff, sum1, 2);
            l0 = l0 * alpha0 + sum0;  m0 = mx0;
            l1 = l1 * alpha1 + sum1;  m1 = mx1;

            unsigned pa[2][4];
            #pragma unroll
            for (int t16 = 0; t16 < 2; t16++) {
                pa[t16][0] = h2pack(s[2 * t16][0],     s[2 * t16][1]);
                pa[t16][1] = h2pack(s[2 * t16][2],     s[2 * t16][3]);
                pa[t16][2] = h2pack(s[2 * t16 + 1][0], s[2 * t16 + 1][1]);
                pa[t16][3] = h2pack(s[2 * t16 + 1][2], s[2 * t16 + 1][3]);
            }

            // O-rescale only if any lane's max advanced (exact skip: alpha==1)
            if (!__all_sync(0xffffffff, (alpha0 == 1.f) && (alpha1 == 1.f))) {
                #pragma unroll
                for (int nt = 0; nt < 16; nt++) {
                    O[nt][0] *= alpha0; O[nt][1] *= alpha0;
                    O[nt][2] *= alpha1; O[nt][3] *= alpha1;
                }
            }

            // ---- PV ----
            #pragma unroll
            for (int t16 = 0; t16 < 2; t16++) {
                int kpb = half * 16 + t16 * 8;
                #pragma unroll
                for (int nt = 0; nt < 16; nt++) {
                    int n = nt * 8 + lr;
                    unsigned b0 = Vp[(kpb + lc) * VPSTR + n];
                    unsigned b1 = Vp[(kpb + 4 + lc) * VPSTR + n];
                    mma_f16(O[nt], pa[t16][0], pa[t16][1], pa[t16][2], pa[t16][3], b0, b1);
                }
            }
        }
        bcur = bnext;
    }

    // epilogue
    float linv0 = 1.f / l0;
    float linv1 = 1.f / l1;
    int r0 = qb + wRow + lr;
    int r1 = r0 + 8;
    unsigned* outvW = (unsigned*)outv;
    unsigned* outgW = (unsigned*)outg;
    #pragma unroll
    for (int nt = 0; nt < 16; nt++) {
        int c = nt * 8 + 2 * lc;
        unsigned w0 = h2pack(O[nt][0] * linv0, O[nt][1] * linv0);
        unsigned w1 = h2pack(O[nt][2] * linv1, O[nt][3] * linv1);
        if (c < 32) {
            outvW[(size_t)r0 * 128 + (hof + c) / 2] = w0;
            outvW[(size_t)r1 * 128 + (hof + c) / 2] = w1;
        } else {
            int ch = (c - 32) >> 5;
            int d  = (c - 32) & 31;
            outgW[((size_t)r0 * 3 + ch) * 128 + (hof + d) / 2] = w0;
            outgW[((size_t)r1 * 3 + ch) * 128 + (hof + d) / 2] = w1;
        }
    }
}

// ---------------------------------------------------------------------------
// Host orchestration (multi-stream fork/join, capture-safe)
// ---------------------------------------------------------------------------
extern "C" void kernel_launch(void* const* d_in, const int* in_sizes, int n_in,
                              void* d_out, int out_size)
{
    const float* equ    = (const float*)d_in[0];
    const float* h      = (const float*)d_in[1];
    const float* W_equ  = (const float*)d_in[4];
    const float* W_gproj= (const float*)d_in[5];
    const float* W_vg   = (const float*)d_in[6];
    const float* W_g1   = (const float*)d_in[7];
    const float* b_g1   = (const float*)d_in[8];
    const float* W_g2   = (const float*)d_in[9];
    const float* b_g2   = (const float*)d_in[10];
    const float* W_q    = (const float*)d_in[11];
    const float* b_q    = (const float*)d_in[12];
    const float* W_k    = (const float*)d_in[13];
    const float* b_k    = (const float*)d_in[14];
    const float* W_v    = (const float*)d_in[15];
    const float* b_v    = (const float*)d_in[16];
    const float* W_ng   = (const float*)d_in[17];
    const float* b_ng   = (const float*)d_in[18];
    const float* W_gout = (const float*)d_in[19];
    const float* W_gdec = (const float*)d_in[20];
    const float* W_hdec = (const float*)d_in[21];
    const float* b_hdec = (const float*)d_in[22];

    float* out = (float*)d_out;

    static cudaStream_t s1 = nullptr, s2 = nullptr;
    static cudaEvent_t evRoot, evPrep, evPack, evH2, evVg, evAttn, evS1, evHout;
    if (!s1) {
        cudaStreamCreateWithFlags(&s1, cudaStreamNonBlocking);
        cudaStreamCreateWithFlags(&s2, cudaStreamNonBlocking);
        cudaEventCreateWithFlags(&evRoot, cudaEventDisableTiming);
        cudaEventCreateWithFlags(&evPrep, cudaEventDisableTiming);
        cudaEventCreateWithFlags(&evPack, cudaEventDisableTiming);
        cudaEventCreateWithFlags(&evH2, cudaEventDisableTiming);
        cudaEventCreateWithFlags(&evVg, cudaEventDisableTiming);
        cudaEventCreateWithFlags(&evAttn, cudaEventDisableTiming);
        cudaEventCreateWithFlags(&evS1, cudaEventDisableTiming);
        cudaEventCreateWithFlags(&evHout, cudaEventDisableTiming);
    }

    float* S = nullptr;
    cudaGetSymbolAddress((void**)&S, scratch);

    const int SM1 = (3 * ASZ + 3 * BSZ) * 4;        // 41472
    const int SM3 = SM1 * 2;                        // 82944
    cudaFuncSetAttribute(hgemm<1, true>,  cudaFuncAttributeMaxDynamicSharedMemorySize, SM1);
    cudaFuncSetAttribute(hgemm<1, false>, cudaFuncAttributeMaxDynamicSharedMemorySize, SM1);
    cudaFuncSetAttribute(hgemm<3, false>, cudaFuncAttributeMaxDynamicSharedMemorySize, SM3);
    cudaFuncSetAttribute(qkv_hgemm, cudaFuncAttributeMaxDynamicSharedMemorySize, SM3);
    cudaFuncSetAttribute(attn_kernel, cudaFuncAttributeMaxDynamicSharedMemorySize, ATTN_SMEM);

    __half* gram_h = (__half*)(S + OFF_GRAM);
    __half* hid_h  = (__half*)(S + OFF_HID);
    __half* h2hi   = (__half*)(S + OFF_H2HI);
    __half* h2lo   = (__half*)(S + OFF_H2LO);
    __half* qhi    = (__half*)(S + OFF_QHI);
    __half* qlo    = (__half*)(S + OFF_QLO);
    __half* khi    = (__half*)(S + OFF_KHI);
    __half* klo    = (__half*)(S + OFF_KLO);
    unsigned* vpair= (unsigned*)(S + OFF_VPAIR);
    __half* outv_h = (__half*)(S + OFF_OUTV);
    __half* outg_h = (__half*)(S + OFF_OUTG);
    float*  hpre   = S + OFF_HPRE;
    unsigned* Pg1  = (unsigned*)(S + OFF_PG1);
    unsigned* Pg2  = (unsigned*)(S + OFF_PG2);
    unsigned* Pqh  = (unsigned*)(S + OFF_PQH);
    unsigned* Pql  = (unsigned*)(S + OFF_PQL);
    unsigned* Pkh  = (unsigned*)(S + OFF_PKH);
    unsigned* Pkl  = (unsigned*)(S + OFF_PKL);
    unsigned* Pv   = (unsigned*)(S + OFF_PV);
    unsigned* Phdh = (unsigned*)(S + OFF_PHDH);
    unsigned* Phdl = (unsigned*)(S + OFF_PHDL);
    unsigned* W3p  = (unsigned*)(S + OFF_W3P);
    float* Wg      = S + OFF_WG;
    float* W1      = S + OFF_W1;
    float* Wvg2    = S + OFF_WVG2;
    float* W2f     = S + OFF_W2F;
    float* bias2   = S + OFF_BIAS2;

    // q scaling includes log2(e) for exp2-based softmax
    const float qalpha = 0.17677669529663687f * 1.4426950408889634f;

    // ---- fork ----
    cudaEventRecord(evRoot, 0);
    cudaStreamWaitEvent(s1, evRoot, 0);
    cudaStreamWaitEvent(s2, evRoot, 0);

    // s2: h2fill early (only needs h)
    h2fill_kernel<<<(NN * EE + 255) / 256, 256, 0, s2>>>(h, h2hi, h2lo);
    cudaEventRecord(evH2, s2);

    // s1: weight packing + W3/bias2 + hpre
    pack_weights<<<2176, 256, 0, s1>>>(W_g1, W_g2, W_q, W_k, W_v, W_hdec,
                                       Pg1, Pg2, Pqh, Pql, Pkh, Pkl, Pv, Phdh, Phdl);
    cudaEventRecord(evPack, s1);
    prep_w3<<<129, 256, 0, s1>>>(W_ng, W_hdec, b_ng, b_hdec, W3p, bias2);
    cudaStreamWaitEvent(s1, evH2, 0);
    hgemm<3, false><<<dim3(2, 64), 256, SM3, s1>>>(h2hi + 256, h2lo + 256, 512,
                                                   Phdh, Phdl, 256,
                                                   bias2, nullptr, 0, 0.f, 1.f,
                                                   hpre, nullptr, nullptr, 256, 256);
    cudaEventRecord(evS1, s1);

    // main: prep combos
    prep_small<<<35, 256>>>(W_equ, W_gproj, W_gdec, W_vg, W_gout, Wg, W1, Wvg2, W2f);
    cudaEventRecord(evPrep, 0);

    // s2: vg -> vpair direct
    cudaStreamWaitEvent(s2, evPrep, 0);
    vg_small<<<192, 256, 0, s2>>>(equ, Wvg2, (__half*)vpair);
    cudaEventRecord(evVg, s2);

    // main: gram -> MLP -> qkv -> attention
    g2p_gram<<<NN, 128>>>(equ, Wg, gram_h);
    cudaStreamWaitEvent(0, evPack, 0);
    hgemm<1, true><<<dim3(4, 64), 256, SM1>>>(gram_h, nullptr, 1024, Pg1, nullptr, 512,
                                              b_g1, nullptr, 0, 0.f, 1.f,
                                              nullptr, hid_h, nullptr, 512, 1024);
    hgemm<1, false><<<dim3(2, 64), 256, SM1>>>(hid_h, nullptr, 512, Pg2, nullptr, 256,
                                               b_g2, nullptr, 0, 0.f, 1.f,
                                               nullptr, h2hi, h2lo, 512, 512);
    cudaStreamWaitEvent(0, evH2, 0);
    qkv_hgemm<<<dim3(2, 64, 3), 256, SM3>>>(h2hi, h2lo, Pqh, Pql, Pkh, Pkl, Pv,
                                            b_q, b_k, b_v, qhi, qlo, khi, klo,
                                            (__half*)vpair, qalpha);
    cudaStreamWaitEvent(0, evVg, 0);
    attn_kernel<<<dim3(NN / AQ, HH), 256, ATTN_SMEM>>>(
        (const unsigned*)qhi, (const unsigned*)qlo,
        (const unsigned*)khi, (const unsigned*)klo,
        vpair, outv_h, outg_h);
    cudaEventRecord(evAttn, 0);

    // s2: h_out = outv@W3 + hpre
    cudaStreamWaitEvent(s2, evAttn, 0);
    cudaStreamWaitEvent(s2, evS1, 0);
    hgemm<1, false><<<dim3(2, 64), 256, SM1, s2>>>(outv_h, nullptr, 256, W3p, nullptr, 256,
                                                   nullptr, hpre, 256, 1.f, 1.f,
                                                   out + (size_t)ROWS * MMDIM,
                                                   nullptr, nullptr, 256, 256);
    cudaEventRecord(evHout, s2);

    // main: equ_out = equ@W1 + outg@W2f
    equ_out_kernel<<<768, 256>>>(equ, outg_h, W1, W2f, out);

    // ---- join ----
    cudaStreamWaitEvent(0, evHout, 0);
}

// round 13
// speedup vs baseline: 1.0435x; 1.0435x over previous
#include <cuda_runtime.h>
#include <cuda_fp16.h>
#include <math.h>

#define NN 4096
#define NV 3
#define MMDIM 16
#define EE 256
#define HH 8
#define DD 32
#define ROWS (NN*NV)

__device__ float scratch[26607616];

// word offsets
#define OFF_GRAM    0u
#define OFF_HID     2097152u
#define OFF_H2HI    3145728u
#define OFF_H2LO    4194304u
#define OFF_QHI     5242880u
#define OFF_QLO     5767168u
#define OFF_KHI     6291456u
#define OFF_KLO     6815744u
#define OFF_VPAIR   9437184u
#define OFF_OUTV    11534336u
#define OFF_OUTG    12058624u
#define OFF_HPRE    13631488u
#define OFF_PG1     14680064u
#define OFF_PG2     14942208u
#define OFF_PQH     15007744u
#define OFF_PQL     15073280u
#define OFF_PKH     15138816u
#define OFF_PKL     15204352u
#define OFF_PV      15269888u
#define OFF_PHDH    15335424u
#define OFF_PHDL    15368192u
#define OFF_W3P     15400960u
#define OFF_WG      15433728u
#define OFF_W1      15434240u
#define OFF_WVG2    15434496u
#define OFF_W2F     15438592u
#define OFF_BIAS2   15442688u

// ---------------------------------------------------------------------------
// helpers
// ---------------------------------------------------------------------------
__device__ __forceinline__ void mma_f16(float c[4],
                                        unsigned a0, unsigned a1, unsigned a2, unsigned a3,
                                        unsigned b0, unsigned b1) {
    asm volatile(
        "mma.sync.aligned.m16n8k16.row.col.f32.f16.f16.f32 "
        "{%0,%1,%2,%3}, {%4,%5,%6,%7}, {%8,%9}, {%0,%1,%2,%3};"
        : "+f"(c[0]), "+f"(c[1]), "+f"(c[2]), "+f"(c[3])
        : "r"(a0), "r"(a1), "r"(a2), "r"(a3), "r"(b0), "r"(b1));
}

__device__ __forceinline__ unsigned h2pack(float a, float b) {
    __half2 h = __floats2half2_rn(a, b);
    return *(unsigned*)&h;
}

__device__ __forceinline__ void cp_async16(void* smem, const void* gmem) {
    unsigned s = (unsigned)__cvta_generic_to_shared(smem);
    asm volatile("cp.async.cg.shared.global [%0], [%1], 16;" :: "r"(s), "l"(gmem));
}
#define CP_COMMIT() asm volatile("cp.async.commit_group;")
#define CP_WAIT(n)  asm volatile("cp.async.wait_group %0;" :: "n"(n))

// ---------------------------------------------------------------------------
// Weight packing (half2 kp-pairs)
// ---------------------------------------------------------------------------
__device__ __forceinline__ void pack_one(const float* __restrict__ W, int N, int i,
                                         unsigned* __restrict__ H, unsigned* __restrict__ L)
{
    int kp = i / N, n = i - kp * N;
    float x0 = W[(size_t)(2 * kp) * N + n];
    float x1 = W[(size_t)(2 * kp + 1) * N + n];
    __half h0 = __float2half_rn(x0), h1 = __float2half_rn(x1);
    __half2 hh = __halves2half2(h0, h1);
    H[i] = *(unsigned*)&hh;
    if (L) {
        __half2 ll = __floats2half2_rn(x0 - __half2float(h0), x1 - __half2float(h1));
        L[i] = *(unsigned*)&ll;
    }
}

__global__ void pack_weights(const float* Wg1, const float* Wg2, const float* Wq,
                             const float* Wk, const float* Wv, const float* Whd,
                             unsigned* Pg1, unsigned* Pg2,
                             unsigned* Pqh, unsigned* Pql,
                             unsigned* Pkh, unsigned* Pkl,
                             unsigned* Pv, unsigned* Phdh, unsigned* Phdl)
{
    int idx = blockIdx.x * 256 + threadIdx.x;
    if (idx < 262144) { pack_one(Wg1, 512, idx, Pg1, nullptr); return; }
    idx -= 262144;
    if (idx < 65536) { pack_one(Wg2, 256, idx, Pg2, nullptr); return; }
    idx -= 65536;
    if (idx < 65536) { pack_one(Wq, 256, idx, Pqh, Pql); return; }
    idx -= 65536;
    if (idx < 65536) { pack_one(Wk, 256, idx, Pkh, Pkl); return; }
    idx -= 65536;
    if (idx < 65536) { pack_one(Wv, 256, idx, Pv, nullptr); return; }
    idx -= 65536;
    if (idx < 32768) { pack_one(Whd, 256, idx, Phdh, Phdl); return; }
}

// ---------------------------------------------------------------------------
// Prep: small weight combinations (fp32)
// ---------------------------------------------------------------------------
__global__ void prep_small(const float* __restrict__ We, const float* __restrict__ Wgp,
                           const float* __restrict__ Wgd, const float* __restrict__ Wvg,
                           const float* __restrict__ Wgo,
                           float* Wg, float* W1, float* Wvg2, float* W2f)
{
    int idx = blockIdx.x * 256 + threadIdx.x;
    if (idx < 512) {
        int m = idx >> 5, n = idx & 31;
        float a = 0;
        for (int e = 0; e < 256; e++) a += We[m * 256 + e] * Wgp[e * 32 + n];
        Wg[idx] = 16.f * a; return;
    }
    idx -= 512;
    if (idx < 256) {
        int m = idx >> 4, j = idx & 15;
        float a = 0;
        for (int e = 0; e < 256; e++) a += We[m * 256 + e] * Wgd[e * 16 + j];
        W1[idx] = 16.f * a; return;
    }
    idx -= 256;
    if (idx < 4096) {
        int m = idx >> 8, c = idx & 255;
        float a = 0;
        for (int e = 0; e < 256; e++) a += We[m * 256 + e] * Wvg[e * 256 + c];
        Wvg2[idx] = 16.f * a; return;
    }
    idx -= 4096;
    if (idx < 4096) {
        int k = idx >> 4, j = idx & 15;
        float a = 0;
        for (int e = 0; e < 256; e++) a += Wgo[k * 256 + e] * Wgd[e * 16 + j];
        W2f[idx] = a;
    }
}

// W3p = pack(W_ng @ W_hdec); bias2 = b_ng@W_hdec + b_hdec
__global__ void prep_w3(const float* __restrict__ Wng, const float* __restrict__ Whd,
                        const float* __restrict__ bng, const float* __restrict__ bhd,
                        unsigned* W3p, float* bias2)
{
    int idx = blockIdx.x * 256 + threadIdx.x;
    if (idx < 32768) {
        int kp = idx >> 8, n = idx & 255;
        float a0 = 0, a1 = 0;
        for (int e = 0; e < 256; e++) {
            float w = Whd[e * 256 + n];
            a0 += Wng[(2 * kp) * 256 + e] * w;
            a1 += Wng[(2 * kp + 1) * 256 + e] * w;
        }
        __half2 h = __floats2half2_rn(a0, a1);
        W3p[idx] = *(unsigned*)&h;
        return;
    }
    idx -= 32768;
    if (idx < 256) {
        float a = bhd[idx];
        for (int k = 0; k < 256; k++) a += bng[k] * Whd[k * 256 + idx];
        bias2[idx] = a;
    }
}

// ---------------------------------------------------------------------------
// Fused g2p + gram
// ---------------------------------------------------------------------------
__global__ __launch_bounds__(128)
void g2p_gram(const float* __restrict__ equ, const float* __restrict__ Wg,
              __half* __restrict__ gram)
{
    __shared__ float wgs[512];
    __shared__ float es[48];
    __shared__ float g2s[96];
    int t = threadIdx.x;
    int node = blockIdx.x;
    #pragma unroll
    for (int i = 0; i < 4; i++) wgs[t + i * 128] = Wg[t + i * 128];
    if (t < 48) es[t] = equ[(size_t)node * 48 + t];
    __syncthreads();
    if (t < 96) {
        int i = t >> 5, a = t & 31;
        float acc = 0;
        #pragma unroll
        for (int k = 0; k < 16; k++) acc += es[i * 16 + k] * wgs[k * 32 + a];
        g2s[t] = acc;
    }
    __syncthreads();
    #pragma unroll
    for (int o = t; o < 1024; o += 128) {
        int a = o >> 5, b = o & 31;
        gram[(size_t)node * 1024 + o] = __float2half_rn(
            g2s[a] * g2s[b] + g2s[32 + a] * g2s[32 + b] + g2s[64 + a] * g2s[64 + b]);
    }
}

// vg = equ @ Wvg2 (K=16), written directly into paired attention layout.
__global__ __launch_bounds__(256)
void vg_small(const float* __restrict__ equ, const float* __restrict__ Wvg2,
              __half* __restrict__ vpH)
{
    __shared__ float ws[16 * 256];
    __shared__ float es[64 * 16];
    int tid = threadIdx.x;
    #pragma unroll
    for (int i = 0; i < 16; i++) ws[tid + i * 256] = Wvg2[tid + i * 256];
    int r0 = blockIdx.x * 64;
    #pragma unroll
    for (int i = 0; i < 4; i++) {
        int idx = tid + i * 256;
        es[idx] = equ[(size_t)r0 * 16 + idx];
    }
    __syncthreads();
    const int head = tid >> 5, d = tid & 31;
    for (int r = 0; r < 64; r++) {
        float acc = 0;
        #pragma unroll
        for (int k = 0; k < 16; k++) acc += es[r * 16 + k] * ws[k * 256 + tid];
        int gr = r0 + r;
        int node = gr / 3;
        int ch = gr - 3 * node;
        size_t w = ((size_t)(node >> 1) * 1024 + head * 128 + 32 + ch * 32 + d) * 2 + (node & 1);
        vpH[w] = __float2half_rn(acc);
    }
}

// h2 right half = 16h split hi/lo
__global__ void h2fill_kernel(const float* __restrict__ h,
                              __half* __restrict__ h2hi, __half* __restrict__ h2lo)
{
    int idx = blockIdx.x * blockDim.x + threadIdx.x;
    if (idx < NN * EE) {
        int r = idx >> 8, c = idx & 255;
        float v = 16.f * h[idx];
        __half hi = __float2half_rn(v);
        size_t o = (size_t)r * 512 + 256 + c;
        h2hi[o] = hi;
        h2lo[o] = __float2half_rn(v - __half2float(hi));
    }
}

// equ_out = equ@W1 + outg@W2f  (N=16 fused)
__global__ __launch_bounds__(256)
void equ_out_kernel(const float* __restrict__ equ, const __half* __restrict__ outg,
                    const float* __restrict__ W1, const float* __restrict__ W2,
                    float* __restrict__ out)
{
    __shared__ float w1s[256];
    __shared__ float w2s[4096];
    int tid = threadIdx.x;
    w1s[tid] = W1[tid];
    #pragma unroll
    for (int i = 0; i < 16; i++) w2s[tid + i * 256] = W2[tid + i * 256];
    __syncthreads();
    int lane = tid & 31, warp = tid >> 5;
    int row = blockIdx.x * 16 + warp * 2 + (lane >> 4);
    int j = lane & 15;
    float acc = 0;
    const float* er = equ + (size_t)row * 16;
    #pragma unroll
    for (int k = 0; k < 16; k++) acc += er[k] * w1s[k * 16 + j];
    const __half2* og = (const __half2*)(outg + (size_t)row * 256);
    #pragma unroll 8
    for (int kp = 0; kp < 128; kp++) {
        float2 v = __half22float2(og[kp]);
        acc += v.x * w2s[(2 * kp) * 16 + j] + v.y * w2s[(2 * kp + 1) * 16 + j];
    }
    out[(size_t)row * 16 + j] = acc;
}

// ---------------------------------------------------------------------------
// FP16 GEMM, 64x128 tile (8 warps, warp tile 32x32), 3-stage cp.async pipeline.
// ---------------------------------------------------------------------------
#define HA_STR 20
#define HB_STR 136
#define ASZ (64*HA_STR)
#define BSZ (16*HB_STR)

__device__ __forceinline__ void epi_store(float v0, float v1,
                                          float* outF, __half* outH, __half* outL,
                                          size_t off)
{
    if (outF) {
        *(float2*)&outF[off] = make_float2(v0, v1);
    } else if (outL) {
        __half h0 = __float2half_rn(v0), h1 = __float2half_rn(v1);
        __half2 hh = __halves2half2(h0, h1);
        ((__half2*)outH)[off >> 1] = hh;
        ((__half2*)outL)[off >> 1] =
            __floats2half2_rn(v0 - __half2float(h0), v1 - __half2float(h1));
    } else {
        ((__half2*)outH)[off >> 1] = __floats2half2_rn(v0, v1);
    }
}

#define STAGE_A_G(SRC, DST, K0) { \
    int row_ = tid >> 2, seg_ = tid & 3; \
    cp_async16(&(DST)[row_ * HA_STR + seg_ * 4], \
               &(SRC)[(size_t)(bm + row_) * lda + (K0) + seg_ * 8]); }
#define STAGE_B_G(SRC, DST, K0) { \
    _Pragma("unroll") \
    for (int i = 0; i < 2; i++) { \
        int idx = tid + i * 256; \
        int kp = idx >> 5, s = idx & 31; \
        cp_async16(&(DST)[kp * HB_STR + s * 4], \
                   &(SRC)[(size_t)(((K0) >> 1) + kp) * ldbw + bn + s * 4]); \
    } }

template<int NPASS, bool RELU>
__global__ __launch_bounds__(256)
void hgemm(const __half* __restrict__ A, const __half* __restrict__ Al, int lda,
           const unsigned* __restrict__ Bp, const unsigned* __restrict__ Bl, int ldbw,
           const float* __restrict__ bias,
           const float* __restrict__ Res, int ldres, float resScale, float alpha,
           float* __restrict__ outF, __half* __restrict__ outH, __half* __restrict__ outL,
           int ldc, int K)
{
    extern __shared__ unsigned smw[];
    unsigned* As  = smw;
    unsigned* Bs  = smw + 3 * ASZ;
    unsigned* Als = Bs + 3 * BSZ;
    unsigned* Bls = Als + 3 * ASZ;

    const int tid  = threadIdx.x;
    const int lane = tid & 31;
    const int warp = tid >> 5;
    const int bm   = blockIdx.y * 64;
    const int bn   = blockIdx.x * 128;
    const int wM   = (warp >> 2) * 32;
    const int wN   = (warp & 3) * 32;
    const int lr   = lane >> 2;
    const int lc   = lane & 3;

    float acc[2][4][4] = {};
    const int KT = K / 32;

    STAGE_A_G(A, As, 0);
    if (NPASS == 3) STAGE_A_G(Al, Als, 0);
    STAGE_B_G(Bp, Bs, 0);
    if (NPASS == 3) STAGE_B_G(Bl, Bls, 0);
    CP_COMMIT();
    STAGE_A_G(A, As + ASZ, 32);
    if (NPASS == 3) STAGE_A_G(Al, Als + ASZ, 32);
    STAGE_B_G(Bp, Bs + BSZ, 32);
    if (NPASS == 3) STAGE_B_G(Bl, Bls + BSZ, 32);
    CP_COMMIT();

    int scur = 0;
    for (int kt = 0; kt < KT; kt++) {
        if (kt + 2 < KT) {
            int s2 = scur + 2; if (s2 >= 3) s2 -= 3;
            int k0 = (kt + 2) * 32;
            STAGE_A_G(A, As + s2 * ASZ, k0);
            if (NPASS == 3) STAGE_A_G(Al, Als + s2 * ASZ, k0);
            STAGE_B_G(Bp, Bs + s2 * BSZ, k0);
            if (NPASS == 3) STAGE_B_G(Bl, Bls + s2 * BSZ, k0);
            CP_COMMIT();
            CP_WAIT(2);
        } else if (kt + 1 < KT) {
            CP_WAIT(1);
        } else {
            CP_WAIT(0);
        }
        __syncthreads();

        const unsigned* Ac  = As  + scur * ASZ;
        const unsigned* Bc  = Bs  + scur * BSZ;
        const unsigned* Alc = Als + scur * ASZ;
        const unsigned* Blc = Bls + scur * BSZ;

        #pragma unroll
        for (int ks = 0; ks < 2; ks++) {
            unsigned ah[2][4], al[2][4];
            #pragma unroll
            for (int mt = 0; mt < 2; mt++) {
                int rb = wM + mt * 16 + lr;
                int c  = ks * 8 + lc;
                ah[mt][0] = Ac[rb * HA_STR + c];
                ah[mt][1] = Ac[(rb + 8) * HA_STR + c];
                ah[mt][2] = Ac[rb * HA_STR + c + 4];
                ah[mt][3] = Ac[(rb + 8) * HA_STR + c + 4];
                if (NPASS == 3) {
                    al[mt][0] = Alc[rb * HA_STR + c];
                    al[mt][1] = Alc[(rb + 8) * HA_STR + c];
                    al[mt][2] = Alc[rb * HA_STR + c + 4];
                    al[mt][3] = Alc[(rb + 8) * HA_STR + c + 4];
                }
            }
            unsigned bh[4][2], bl[4][2];
            #pragma unroll
            for (int nt = 0; nt < 4; nt++) {
                int n  = wN + nt * 8 + lr;
                int kp = ks * 8 + lc;
                bh[nt][0] = Bc[kp * HB_STR + n];
                bh[nt][1] = Bc[(kp + 4) * HB_STR + n];
                if (NPASS == 3) {
                    bl[nt][0] = Blc[kp * HB_STR + n];
                    bl[nt][1] = Blc[(kp + 4) * HB_STR + n];
                }
            }
            #pragma unroll
            for (int mt = 0; mt < 2; mt++)
                #pragma unroll
                for (int nt = 0; nt < 4; nt++) {
                    mma_f16(acc[mt][nt], ah[mt][0], ah[mt][1], ah[mt][2], ah[mt][3],
                            bh[nt][0], bh[nt][1]);
                    if (NPASS == 3) {
                        mma_f16(acc[mt][nt], ah[mt][0], ah[mt][1], ah[mt][2], ah[mt][3],
                                bl[nt][0], bl[nt][1]);
                        mma_f16(acc[mt][nt], al[mt][0], al[mt][1], al[mt][2], al[mt][3],
                                bh[nt][0], bh[nt][1]);
                    }
                }
        }
        __syncthreads();
        scur = scur + 1; if (scur == 3) scur = 0;
    }

    #pragma unroll
    for (int mt = 0; mt < 2; mt++) {
        #pragma unroll
        for (int nt = 0; nt < 4; nt++) {
            int col = bn + wN + nt * 8 + 2 * lc;
            #pragma unroll
            for (int half = 0; half < 2; half++) {
                int r = bm + wM + mt * 16 + lr + half * 8;
                float v0 = acc[mt][nt][half * 2 + 0];
                float v1 = acc[mt][nt][half * 2 + 1];
                if (bias) { v0 += bias[col]; v1 += bias[col + 1]; }
                v0 *= alpha; v1 *= alpha;
                if (Res) {
                    v0 = fmaf(resScale, Res[(size_t)r * ldres + col], v0);
                    v1 = fmaf(resScale, Res[(size_t)r * ldres + col + 1], v1);
                }
                if (RELU) { v0 = fmaxf(v0, 0.f); v1 = fmaxf(v1, 0.f); }
                epi_store(v0, v1, outF, outH, outL, (size_t)r * ldc + col);
            }
        }
    }
}

// ---------------------------------------------------------------------------
// Fused QKV (q/k x3 split-out; v x1 direct to vpair layout). 64x128 tiles.
// ---------------------------------------------------------------------------
__global__ __launch_bounds__(256)
void qkv_hgemm(const __half* __restrict__ A, const __half* __restrict__ Al,
               const unsigned* __restrict__ Pqh, const unsigned* __restrict__ Pql,
               const unsigned* __restrict__ Pkh, const unsigned* __restrict__ Pkl,
               const unsigned* __restrict__ Pv,
               const float* __restrict__ bq, const float* __restrict__ bk,
               const float* __restrict__ bv,
               __half* qh, __half* ql, __half* kh, __half* kl,
               __half* __restrict__ vpH,
               float qalpha)
{
    extern __shared__ unsigned smw[];
    unsigned* As  = smw;
    unsigned* Bs  = smw + 3 * ASZ;
    unsigned* Als = Bs + 3 * BSZ;
    unsigned* Bls = Als + 3 * ASZ;

    const int seg = blockIdx.z;
    const bool x3 = (seg < 2);
    const unsigned* Bp = (seg == 0) ? Pqh : (seg == 1) ? Pkh : Pv;
    const unsigned* Bl = (seg == 0) ? Pql : (seg == 1) ? Pkl : nullptr;
    const float* bias  = (seg == 0) ? bq : (seg == 1) ? bk : bv;
    __half* outH = (seg == 0) ? qh : kh;
    __half* outL = (seg == 0) ? ql : kl;
    const float alpha = (seg == 0) ? qalpha : 1.f;
    const int lda = 512, ldbw = 256, ldc = 256, K = 512;

    const int tid  = threadIdx.x;
    const int lane = tid & 31;
    const int warp = tid >> 5;
    const int bm   = blockIdx.y * 64;
    const int bn   = blockIdx.x * 128;
    const int wM   = (warp >> 2) * 32;
    const int wN   = (warp & 3) * 32;
    const int lr   = lane >> 2;
    const int lc   = lane & 3;

    float acc[2][4][4] = {};
    const int KT = K / 32;

    STAGE_A_G(A, As, 0);
    if (x3) STAGE_A_G(Al, Als, 0);
    STAGE_B_G(Bp, Bs, 0);
    if (x3) STAGE_B_G(Bl, Bls, 0);
    CP_COMMIT();
    STAGE_A_G(A, As + ASZ, 32);
    if (x3) STAGE_A_G(Al, Als + ASZ, 32);
    STAGE_B_G(Bp, Bs + BSZ, 32);
    if (x3) STAGE_B_G(Bl, Bls + BSZ, 32);
    CP_COMMIT();

    int scur = 0;
    for (int kt = 0; kt < KT; kt++) {
        if (kt + 2 < KT) {
            int s2 = scur + 2; if (s2 >= 3) s2 -= 3;
            int k0 = (kt + 2) * 32;
            STAGE_A_G(A, As + s2 * ASZ, k0);
            if (x3) STAGE_A_G(Al, Als + s2 * ASZ, k0);
            STAGE_B_G(Bp, Bs + s2 * BSZ, k0);
            if (x3) STAGE_B_G(Bl, Bls + s2 * BSZ, k0);
            CP_COMMIT();
            CP_WAIT(2);
        } else if (kt + 1 < KT) {
            CP_WAIT(1);
        } else {
            CP_WAIT(0);
        }
        __syncthreads();

        const unsigned* Ac  = As  + scur * ASZ;
        const unsigned* Bc  = Bs  + scur * BSZ;
        const unsigned* Alc = Als + scur * ASZ;
        const unsigned* Blc = Bls + scur * BSZ;

        #pragma unroll
        for (int ks = 0; ks < 2; ks++) {
            unsigned ah[2][4], al[2][4];
            #pragma unroll
            for (int mt = 0; mt < 2; mt++) {
                int rb = wM + mt * 16 + lr;
                int c  = ks * 8 + lc;
                ah[mt][0] = Ac[rb * HA_STR + c];
                ah[mt][1] = Ac[(rb + 8) * HA_STR + c];
                ah[mt][2] = Ac[rb * HA_STR + c + 4];
                ah[mt][3] = Ac[(rb + 8) * HA_STR + c + 4];
                if (x3) {
                    al[mt][0] = Alc[rb * HA_STR + c];
                    al[mt][1] = Alc[(rb + 8) * HA_STR + c];
                    al[mt][2] = Alc[rb * HA_STR + c + 4];
                    al[mt][3] = Alc[(rb + 8) * HA_STR + c + 4];
                }
            }
            unsigned bh[4][2], bl[4][2];
            #pragma unroll
            for (int nt = 0; nt < 4; nt++) {
                int n  = wN + nt * 8 + lr;
                int kp = ks * 8 + lc;
                bh[nt][0] = Bc[kp * HB_STR + n];
                bh[nt][1] = Bc[(kp + 4) * HB_STR + n];
                if (x3) {
                    bl[nt][0] = Blc[kp * HB_STR + n];
                    bl[nt][1] = Blc[(kp + 4) * HB_STR + n];
                }
            }
            #pragma unroll
            for (int mt = 0; mt < 2; mt++)
                #pragma unroll
                for (int nt = 0; nt < 4; nt++) {
                    mma_f16(acc[mt][nt], ah[mt][0], ah[mt][1], ah[mt][2], ah[mt][3],
                            bh[nt][0], bh[nt][1]);
                    if (x3) {
                        mma_f16(acc[mt][nt], ah[mt][0], ah[mt][1], ah[mt][2], ah[mt][3],
                                bl[nt][0], bl[nt][1]);
                        mma_f16(acc[mt][nt], al[mt][0], al[mt][1], al[mt][2], al[mt][3],
                                bh[nt][0], bh[nt][1]);
                    }
                }
        }
        __syncthreads();
        scur = scur + 1; if (scur == 3) scur = 0;
    }

    #pragma unroll
    for (int mt = 0; mt < 2; mt++) {
        #pragma unroll
        for (int nt = 0; nt < 4; nt++) {
            int col = bn + wN + nt * 8 + 2 * lc;
            #pragma unroll
            for (int half = 0; half < 2; half++) {
                int r = bm + wM + mt * 16 + lr + half * 8;
                float v0 = (acc[mt][nt][half * 2 + 0] + bias[col]) * alpha;
                float v1 = (acc[mt][nt][half * 2 + 1] + bias[col + 1]) * alpha;
                if (seg == 2) {
                    int head = col >> 5, d = col & 31;
                    size_t w = ((size_t)(r >> 1) * 1024 + head * 128 + d) * 2 + (r & 1);
                    vpH[w]     = __float2half_rn(v0);
                    vpH[w + 2] = __float2half_rn(v1);
                } else {
                    epi_store(v0, v1, nullptr, outH, outL, (size_t)r * ldc + col);
                }
            }
        }
    }
}

// ---------------------------------------------------------------------------
// Flash attention v10: 4 warps x 32 q-rows (B-frags feed 2 MMAs each ->
// smem crossbar traffic halves), triple-buffered K/V rings, one sync/tile,
// exp2 softmax, warp-voted rescale skip.
// ---------------------------------------------------------------------------
#define AQ 128
#define AK 64
#define QP 20
#define VPSTR 136
#define KBUF 1280
#define VBUF 4352

#define ATTN_WORDS (2560*2 + 3*KBUF*2 + 3*VBUF)   // 25856
#define ATTN_SMEM  (ATTN_WORDS * 4)               // 103424

__global__ __launch_bounds__(128, 2)
void attn_kernel(const unsigned* __restrict__ qhiW, const unsigned* __restrict__ qloW,
                 const unsigned* __restrict__ khiW, const unsigned* __restrict__ kloW,
                 const unsigned* __restrict__ vpW,
                 __half* __restrict__ outv, __half* __restrict__ outg)
{
    extern __shared__ unsigned smw[];
    unsigned* Qhi  = smw;                    // [128][QP]
    unsigned* Qlo  = Qhi + 2560;
    unsigned* Khi3 = Qlo + 2560;             // 3 x [64][QP]
    unsigned* Klo3 = Khi3 + 3 * KBUF;
    unsigned* Vp3  = Klo3 + 3 * KBUF;        // 3 x [32][VPSTR]

    const int head = blockIdx.y;
    const int qb   = blockIdx.x * AQ;
    const int tid  = threadIdx.x;            // 128 threads
    const int lane = tid & 31;
    const int warp = tid >> 5;               // 0..3
    const int hofw = head * 16;
    const int hof  = head * DD;
    const int lr   = lane >> 2;
    const int lc   = lane & 3;
    const int wRow = warp * 32;

    // prologue: V(0) group, then K(0)+Q group  (128-thread staging)
    {
        #pragma unroll
        for (int i = 0; i < 8; i++) {
            int idx = tid + i * 128;
            int pr = idx >> 5, s = idx & 31;
            cp_async16(&Vp3[pr * VPSTR + s * 4],
                       &vpW[(size_t)pr * 1024 + head * 128 + s * 4]);
        }
        CP_COMMIT();
    }
    {
        #pragma unroll
        for (int i = 0; i < 2; i++) {
            int idx = tid + i * 128;
            int key = idx >> 2, seg = idx & 3;
            cp_async16(&Khi3[key * QP + seg * 4], &khiW[(size_t)key * 128 + hofw + seg * 4]);
            cp_async16(&Klo3[key * QP + seg * 4], &kloW[(size_t)key * 128 + hofw + seg * 4]);
        }
        #pragma unroll
        for (int i = 0; i < 4; i++) {
            int idx = tid + i * 128;
            int row = idx >> 2, sg = idx & 3;
            cp_async16(&Qhi[row * QP + sg * 4], &qhiW[(size_t)(qb + row) * 128 + hofw + sg * 4]);
            cp_async16(&Qlo[row * QP + sg * 4], &qloW[(size_t)(qb + row) * 128 + hofw + sg * 4]);
        }
        CP_COMMIT();
    }

    float O[2][16][4] = {};
    float m_[2][2], l_[2][2];
    #pragma unroll
    for (int mt = 0; mt < 2; mt++) {
        m_[mt][0] = -1e30f; m_[mt][1] = -1e30f;
        l_[mt][0] = 0.f;    l_[mt][1] = 0.f;
    }

    int bcur = 0;
    for (int t = 0; t < NN / AK; t++) {
        const bool hasNext = (t + 1 < NN / AK);
        int bnext = bcur + 1; if (bnext == 3) bnext = 0;

        if (hasNext) {
            const int kb1 = (t + 1) * AK;
            unsigned* Vd = Vp3 + bnext * VBUF;
            const int p0 = kb1 >> 1;
            #pragma unroll
            for (int i = 0; i < 8; i++) {
                int idx = tid + i * 128;
                int pr = idx >> 5, s = idx & 31;
                cp_async16(&Vd[pr * VPSTR + s * 4],
                           &vpW[((size_t)(p0 + pr)) * 1024 + head * 128 + s * 4]);
            }
            CP_COMMIT();
            unsigned* Kdh = Khi3 + bnext * KBUF;
            unsigned* Kdl = Klo3 + bnext * KBUF;
            #pragma unroll
            for (int i = 0; i < 2; i++) {
                int idx = tid + i * 128;
                int key = idx >> 2, seg = idx & 3;
                cp_async16(&Kdh[key * QP + seg * 4],
                           &khiW[(size_t)(kb1 + key) * 128 + hofw + seg * 4]);
                cp_async16(&Kdl[key * QP + seg * 4],
                           &kloW[(size_t)(kb1 + key) * 128 + hofw + seg * 4]);
            }
            CP_COMMIT();
            CP_WAIT(2);
        } else {
            CP_WAIT(0);
        }
        __syncthreads();

        const unsigned* Kh = Khi3 + bcur * KBUF;
        const unsigned* Kl = Klo3 + bcur * KBUF;
        const unsigned* Vp = Vp3 + bcur * VBUF;

        #pragma unroll
        for (int half = 0; half < 2; half++) {
            // ---- S = Q K^T (fp16x3), warp covers 32 q rows ----
            float s[2][4][4] = {};
            #pragma unroll
            for (int ks = 0; ks < 2; ks++) {
                int c = ks * 8 + lc;
                unsigned ah[2][4], al[2][4];
                #pragma unroll
                for (int mt = 0; mt < 2; mt++) {
                    int rb = wRow + mt * 16 + lr;
                    ah[mt][0] = Qhi[rb * QP + c];
                    ah[mt][1] = Qhi[(rb + 8) * QP + c];
                    ah[mt][2] = Qhi[rb * QP + c + 4];
                    ah[mt][3] = Qhi[(rb + 8) * QP + c + 4];
                    al[mt][0] = Qlo[rb * QP + c];
                    al[mt][1] = Qlo[(rb + 8) * QP + c];
                    al[mt][2] = Qlo[rb * QP + c + 4];
                    al[mt][3] = Qlo[(rb + 8) * QP + c + 4];
                }
                #pragma unroll
                for (int nt = 0; nt < 4; nt++) {
                    int key = half * 32 + nt * 8 + lr;
                    unsigned bh0 = Kh[key * QP + c];
                    unsigned bh1 = Kh[key * QP + c + 4];
                    unsigned bl0 = Kl[key * QP + c];
                    unsigned bl1 = Kl[key * QP + c + 4];
                    #pragma unroll
                    for (int mt = 0; mt < 2; mt++) {
                        mma_f16(s[mt][nt], ah[mt][0], ah[mt][1], ah[mt][2], ah[mt][3], bh0, bh1);
                        mma_f16(s[mt][nt], ah[mt][0], ah[mt][1], ah[mt][2], ah[mt][3], bl0, bl1);
                        mma_f16(s[mt][nt], al[mt][0], al[mt][1], al[mt][2], al[mt][3], bh0, bh1);
                    }
                }
            }

            // ---- online softmax per mt (base 2) ----
            unsigned pa[2][2][4];
            float alpha[2][2];
            #pragma unroll
            for (int mt = 0; mt < 2; mt++) {
                float mx0 = m_[mt][0], mx1 = m_[mt][1];
                #pragma unroll
                for (int nt = 0; nt < 4; nt++) {
                    mx0 = fmaxf(mx0, fmaxf(s[mt][nt][0], s[mt][nt][1]));
                    mx1 = fmaxf(mx1, fmaxf(s[mt][nt][2], s[mt][nt][3]));
                }
                mx0 = fmaxf(mx0, __shfl_xor_sync(0xffffffff, mx0, 1));
                mx0 = fmaxf(mx0, __shfl_xor_sync(0xffffffff, mx0, 2));
                mx1 = fmaxf(mx1, __shfl_xor_sync(0xffffffff, mx1, 1));
                mx1 = fmaxf(mx1, __shfl_xor_sync(0xffffffff, mx1, 2));

                float a0 = exp2f(m_[mt][0] - mx0);
                float a1 = exp2f(m_[mt][1] - mx1);
                float sum0 = 0.f, sum1 = 0.f;
                #pragma unroll
                for (int nt = 0; nt < 4; nt++) {
                    s[mt][nt][0] = exp2f(s[mt][nt][0] - mx0);
                    s[mt][nt][1] = exp2f(s[mt][nt][1] - mx0);
                    s[mt][nt][2] = exp2f(s[mt][nt][2] - mx1);
                    s[mt][nt][3] = exp2f(s[mt][nt][3] - mx1);
                    sum0 += s[mt][nt][0] + s[mt][nt][1];
                    sum1 += s[mt][nt][2] + s[mt][nt][3];
                }
                sum0 += __shfl_xor_sync(0xffffffff, sum0, 1);
                sum0 += __shfl_xor_sync(0xffffffff, sum0, 2);
                sum1 += __shfl_xor_sync(0xffffffff, sum1, 1);
                sum1 += __shfl_xor_sync(0xffffffff, sum1, 2);
                l_[mt][0] = l_[mt][0] * a0 + sum0;  m_[mt][0] = mx0;
                l_[mt][1] = l_[mt][1] * a1 + sum1;  m_[mt][1] = mx1;
                alpha[mt][0] = a0; alpha[mt][1] = a1;

                #pragma unroll
                for (int t16 = 0; t16 < 2; t16++) {
                    pa[mt][t16][0] = h2pack(s[mt][2 * t16][0],     s[mt][2 * t16][1]);
                    pa[mt][t16][1] = h2pack(s[mt][2 * t16][2],     s[mt][2 * t16][3]);
                    pa[mt][t16][2] = h2pack(s[mt][2 * t16 + 1][0], s[mt][2 * t16 + 1][1]);
                    pa[mt][t16][3] = h2pack(s[mt][2 * t16 + 1][2], s[mt][2 * t16 + 1][3]);
                }
            }

            // O-rescale only if any lane's max advanced (exact skip)
            bool noresc = (alpha[0][0] == 1.f) && (alpha[0][1] == 1.f) &&
                          (alpha[1][0] == 1.f) && (alpha[1][1] == 1.f);
            if (!__all_sync(0xffffffff, noresc)) {
                #pragma unroll
                for (int mt = 0; mt < 2; mt++)
                    #pragma unroll
                    for (int nt = 0; nt < 16; nt++) {
                        O[mt][nt][0] *= alpha[mt][0]; O[mt][nt][1] *= alpha[mt][0];
                        O[mt][nt][2] *= alpha[mt][1]; O[mt][nt][3] *= alpha[mt][1];
                    }
            }

            // ---- PV: each B-frag load feeds both mt ----
            #pragma unroll
            for (int t16 = 0; t16 < 2; t16++) {
                int kpb = half * 16 + t16 * 8;
                #pragma unroll
                for (int nt = 0; nt < 16; nt++) {
                    int n = nt * 8 + lr;
                    unsigned b0 = Vp[(kpb + lc) * VPSTR + n];
                    unsigned b1 = Vp[(kpb + 4 + lc) * VPSTR + n];
                    mma_f16(O[0][nt], pa[0][t16][0], pa[0][t16][1], pa[0][t16][2], pa[0][t16][3], b0, b1);
                    mma_f16(O[1][nt], pa[1][t16][0], pa[1][t16][1], pa[1][t16][2], pa[1][t16][3], b0, b1);
                }
            }
        }
        bcur = bnext;
    }

    // epilogue
    unsigned* outvW = (unsigned*)outv;
    unsigned* outgW = (unsigned*)outg;
    #pragma unroll
    for (int mt = 0; mt < 2; mt++) {
        float linv0 = 1.f / l_[mt][0];
        float linv1 = 1.f / l_[mt][1];
        int r0 = qb + wRow + mt * 16 + lr;
        int r1 = r0 + 8;
        #pragma unroll
        for (int nt = 0; nt < 16; nt++) {
            int c = nt * 8 + 2 * lc;
            unsigned w0 = h2pack(O[mt][nt][0] * linv0, O[mt][nt][1] * linv0);
            unsigned w1 = h2pack(O[mt][nt][2] * linv1, O[mt][nt][3] * linv1);
            if (c < 32) {
                outvW[(size_t)r0 * 128 + (hof + c) / 2] = w0;
                outvW[(size_t)r1 * 128 + (hof + c) / 2] = w1;
            } else {
                int ch = (c - 32) >> 5;
                int d  = (c - 32) & 31;
                outgW[((size_t)r0 * 3 + ch) * 128 + (hof + d) / 2] = w0;
                outgW[((size_t)r1 * 3 + ch) * 128 + (hof + d) / 2] = w1;
            }
        }
    }
}

// ---------------------------------------------------------------------------
// Host orchestration (multi-stream fork/join, capture-safe)
// ---------------------------------------------------------------------------
extern "C" void kernel_launch(void* const* d_in, const int* in_sizes, int n_in,
                              void* d_out, int out_size)
{
    const float* equ    = (const float*)d_in[0];
    const float* h      = (const float*)d_in[1];
    const float* W_equ  = (const float*)d_in[4];
    const float* W_gproj= (const float*)d_in[5];
    const float* W_vg   = (const float*)d_in[6];
    const float* W_g1   = (const float*)d_in[7];
    const float* b_g1   = (const float*)d_in[8];
    const float* W_g2   = (const float*)d_in[9];
    const float* b_g2   = (const float*)d_in[10];
    const float* W_q    = (const float*)d_in[11];
    const float* b_q    = (const float*)d_in[12];
    const float* W_k    = (const float*)d_in[13];
    const float* b_k    = (const float*)d_in[14];
    const float* W_v    = (const float*)d_in[15];
    const float* b_v    = (const float*)d_in[16];
    const float* W_ng   = (const float*)d_in[17];
    const float* b_ng   = (const float*)d_in[18];
    const float* W_gout = (const float*)d_in[19];
    const float* W_gdec = (const float*)d_in[20];
    const float* W_hdec = (const float*)d_in[21];
    const float* b_hdec = (const float*)d_in[22];

    float* out = (float*)d_out;

    static cudaStream_t s1 = nullptr, s2 = nullptr;
    static cudaEvent_t evRoot, evPrep, evPack, evH2, evVg, evAttn, evS1, evHout;
    if (!s1) {
        cudaStreamCreateWithFlags(&s1, cudaStreamNonBlocking);
        cudaStreamCreateWithFlags(&s2, cudaStreamNonBlocking);
        cudaEventCreateWithFlags(&evRoot, cudaEventDisableTiming);
        cudaEventCreateWithFlags(&evPrep, cudaEventDisableTiming);
        cudaEventCreateWithFlags(&evPack, cudaEventDisableTiming);
        cudaEventCreateWithFlags(&evH2, cudaEventDisableTiming);
        cudaEventCreateWithFlags(&evVg, cudaEventDisableTiming);
        cudaEventCreateWithFlags(&evAttn, cudaEventDisableTiming);
        cudaEventCreateWithFlags(&evS1, cudaEventDisableTiming);
        cudaEventCreateWithFlags(&evHout, cudaEventDisableTiming);
    }

    float* S = nullptr;
    cudaGetSymbolAddress((void**)&S, scratch);

    const int SM1 = (3 * ASZ + 3 * BSZ) * 4;        // 41472
    const int SM3 = SM1 * 2;                        // 82944
    cudaFuncSetAttribute(hgemm<1, true>,  cudaFuncAttributeMaxDynamicSharedMemorySize, SM1);
    cudaFuncSetAttribute(hgemm<1, false>, cudaFuncAttributeMaxDynamicSharedMemorySize, SM1);
    cudaFuncSetAttribute(hgemm<3, false>, cudaFuncAttributeMaxDynamicSharedMemorySize, SM3);
    cudaFuncSetAttribute(qkv_hgemm, cudaFuncAttributeMaxDynamicSharedMemorySize, SM3);
    cudaFuncSetAttribute(attn_kernel, cudaFuncAttributeMaxDynamicSharedMemorySize, ATTN_SMEM);

    __half* gram_h = (__half*)(S + OFF_GRAM);
    __half* hid_h  = (__half*)(S + OFF_HID);
    __half* h2hi   = (__half*)(S + OFF_H2HI);
    __half* h2lo   = (__half*)(S + OFF_H2LO);
    __half* qhi    = (__half*)(S + OFF_QHI);
    __half* qlo    = (__half*)(S + OFF_QLO);
    __half* khi    = (__half*)(S + OFF_KHI);
    __half* klo    = (__half*)(S + OFF_KLO);
    unsigned* vpair= (unsigned*)(S + OFF_VPAIR);
    __half* outv_h = (__half*)(S + OFF_OUTV);
    __half* outg_h = (__half*)(S + OFF_OUTG);
    float*  hpre   = S + OFF_HPRE;
    unsigned* Pg1  = (unsigned*)(S + OFF_PG1);
    unsigned* Pg2  = (unsigned*)(S + OFF_PG2);
    unsigned* Pqh  = (unsigned*)(S + OFF_PQH);
    unsigned* Pql  = (unsigned*)(S + OFF_PQL);
    unsigned* Pkh  = (unsigned*)(S + OFF_PKH);
    unsigned* Pkl  = (unsigned*)(S + OFF_PKL);
    unsigned* Pv   = (unsigned*)(S + OFF_PV);
    unsigned* Phdh = (unsigned*)(S + OFF_PHDH);
    unsigned* Phdl = (unsigned*)(S + OFF_PHDL);
    unsigned* W3p  = (unsigned*)(S + OFF_W3P);
    float* Wg      = S + OFF_WG;
    float* W1      = S + OFF_W1;
    float* Wvg2    = S + OFF_WVG2;
    float* W2f     = S + OFF_W2F;
    float* bias2   = S + OFF_BIAS2;

    const float qalpha = 0.17677669529663687f * 1.4426950408889634f;

    // ---- fork ----
    cudaEventRecord(evRoot, 0);
    cudaStreamWaitEvent(s1, evRoot, 0);
    cudaStreamWaitEvent(s2, evRoot, 0);

    // s2: h2fill early (only needs h)
    h2fill_kernel<<<(NN * EE + 255) / 256, 256, 0, s2>>>(h, h2hi, h2lo);
    cudaEventRecord(evH2, s2);

    // s1: weight packing + W3/bias2 + hpre
    pack_weights<<<2176, 256, 0, s1>>>(W_g1, W_g2, W_q, W_k, W_v, W_hdec,
                                       Pg1, Pg2, Pqh, Pql, Pkh, Pkl, Pv, Phdh, Phdl);
    cudaEventRecord(evPack, s1);
    prep_w3<<<129, 256, 0, s1>>>(W_ng, W_hdec, b_ng, b_hdec, W3p, bias2);
    cudaStreamWaitEvent(s1, evH2, 0);
    hgemm<3, false><<<dim3(2, 64), 256, SM3, s1>>>(h2hi + 256, h2lo + 256, 512,
                                                   Phdh, Phdl, 256,
                                                   bias2, nullptr, 0, 0.f, 1.f,
                                                   hpre, nullptr, nullptr, 256, 256);
    cudaEventRecord(evS1, s1);

    // main: prep combos
    prep_small<<<35, 256>>>(W_equ, W_gproj, W_gdec, W_vg, W_gout, Wg, W1, Wvg2, W2f);
    cudaEventRecord(evPrep, 0);

    // s2: vg -> vpair direct
    cudaStreamWaitEvent(s2, evPrep, 0);
    vg_small<<<192, 256, 0, s2>>>(equ, Wvg2, (__half*)vpair);
    cudaEventRecord(evVg, s2);

    // main: gram -> MLP -> qkv -> attention
    g2p_gram<<<NN, 128>>>(equ, Wg, gram_h);
    cudaStreamWaitEvent(0, evPack, 0);
    hgemm<1, true><<<dim3(4, 64), 256, SM1>>>(gram_h, nullptr, 1024, Pg1, nullptr, 512,
                                              b_g1, nullptr, 0, 0.f, 1.f,
                                              nullptr, hid_h, nullptr, 512, 1024);
    hgemm<1, false><<<dim3(2, 64), 256, SM1>>>(hid_h, nullptr, 512, Pg2, nullptr, 256,
                                               b_g2, nullptr, 0, 0.f, 1.f,
                                               nullptr, h2hi, h2lo, 512, 512);
    cudaStreamWaitEvent(0, evH2, 0);
    qkv_hgemm<<<dim3(2, 64, 3), 256, SM3>>>(h2hi, h2lo, Pqh, Pql, Pkh, Pkl, Pv,
                                            b_q, b_k, b_v, qhi, qlo, khi, klo,
                                            (__half*)vpair, qalpha);
    cudaStreamWaitEvent(0, evVg, 0);
    attn_kernel<<<dim3(NN / AQ, HH), 128, ATTN_SMEM>>>(
        (const unsigned*)qhi, (const unsigned*)qlo,
        (const unsigned*)khi, (const unsigned*)klo,
        vpair, outv_h, outg_h);
    cudaEventRecord(evAttn, 0);

    // s2: h_out = outv@W3 + hpre
    cudaStreamWaitEvent(s2, evAttn, 0);
    cudaStreamWaitEvent(s2, evS1, 0);
    hgemm<1, false><<<dim3(2, 64), 256, SM1, s2>>>(outv_h, nullptr, 256, W3p, nullptr, 256,
                                                   nullptr, hpre, 256, 1.f, 1.f,
                                                   out + (size_t)ROWS * MMDIM,
                                                   nullptr, nullptr, 256, 256);
    cudaEventRecord(evHout, s2);

    // main: equ_out = equ@W1 + outg@W2f
    equ_out_kernel<<<768, 256>>>(equ, outg_h, W1, W2f, out);

    // ---- join ----
    cudaStreamWaitEvent(0, evHout, 0);
}

// round 14
// speedup vs baseline: 1.0438x; 1.0003x over previous
#include <cuda_runtime.h>
#include <cuda_fp16.h>
#include <math.h>

#define NN 4096
#define NV 3
#define MMDIM 16
#define EE 256
#define HH 8
#define DD 32
#define ROWS (NN*NV)

__device__ float scratch[26607616];

// word offsets
#define OFF_GRAM    0u
#define OFF_HID     2097152u
#define OFF_H2HI    3145728u
#define OFF_H2LO    4194304u
#define OFF_QHI     5242880u
#define OFF_QLO     5767168u
#define OFF_KHI     6291456u
#define OFF_KLO     6815744u
#define OFF_VPAIR   9437184u
#define OFF_OUTV    11534336u
#define OFF_OUTG    12058624u
#define OFF_HPRE    13631488u
#define OFF_PG1     14680064u
#define OFF_PG2     14942208u
#define OFF_PQH     15007744u
#define OFF_PQL     15073280u
#define OFF_PKH     15138816u
#define OFF_PKL     15204352u
#define OFF_PV      15269888u
#define OFF_PHDH    15335424u
#define OFF_PHDL    15368192u
#define OFF_W3P     15400960u
#define OFF_WG      15433728u
#define OFF_W1      15434240u
#define OFF_WVG2    15434496u
#define OFF_W2F     15438592u
#define OFF_BIAS2   15442688u

// ---------------------------------------------------------------------------
// helpers
// ---------------------------------------------------------------------------
__device__ __forceinline__ void mma_f16(float c[4],
                                        unsigned a0, unsigned a1, unsigned a2, unsigned a3,
                                        unsigned b0, unsigned b1) {
    asm volatile(
        "mma.sync.aligned.m16n8k16.row.col.f32.f16.f16.f32 "
        "{%0,%1,%2,%3}, {%4,%5,%6,%7}, {%8,%9}, {%0,%1,%2,%3};"
        : "+f"(c[0]), "+f"(c[1]), "+f"(c[2]), "+f"(c[3])
        : "r"(a0), "r"(a1), "r"(a2), "r"(a3), "r"(b0), "r"(b1));
}

__device__ __forceinline__ unsigned h2pack(float a, float b) {
    __half2 h = __floats2half2_rn(a, b);
    return *(unsigned*)&h;
}

__device__ __forceinline__ void cp_async16(void* smem, const void* gmem) {
    unsigned s = (unsigned)__cvta_generic_to_shared(smem);
    asm volatile("cp.async.cg.shared.global [%0], [%1], 16;" :: "r"(s), "l"(gmem));
}
#define CP_COMMIT() asm volatile("cp.async.commit_group;")
#define CP_WAIT(n)  asm volatile("cp.async.wait_group %0;" :: "n"(n))

// ---------------------------------------------------------------------------
// Weight packing (half2 kp-pairs)
// ---------------------------------------------------------------------------
__device__ __forceinline__ void pack_one(const float* __restrict__ W, int N, int i,
                                         unsigned* __restrict__ H, unsigned* __restrict__ L)
{
    int kp = i / N, n = i - kp * N;
    float x0 = W[(size_t)(2 * kp) * N + n];
    float x1 = W[(size_t)(2 * kp + 1) * N + n];
    __half h0 = __float2half_rn(x0), h1 = __float2half_rn(x1);
    __half2 hh = __halves2half2(h0, h1);
    H[i] = *(unsigned*)&hh;
    if (L) {
        __half2 ll = __floats2half2_rn(x0 - __half2float(h0), x1 - __half2float(h1));
        L[i] = *(unsigned*)&ll;
    }
}

__global__ void pack_weights(const float* Wg1, const float* Wg2, const float* Wq,
                             const float* Wk, const float* Wv, const float* Whd,
                             unsigned* Pg1, unsigned* Pg2,
                             unsigned* Pqh, unsigned* Pql,
                             unsigned* Pkh, unsigned* Pkl,
                             unsigned* Pv, unsigned* Phdh, unsigned* Phdl)
{
    int idx = blockIdx.x * 256 + threadIdx.x;
    if (idx < 262144) { pack_one(Wg1, 512, idx, Pg1, nullptr); return; }
    idx -= 262144;
    if (idx < 65536) { pack_one(Wg2, 256, idx, Pg2, nullptr); return; }
    idx -= 65536;
    if (idx < 65536) { pack_one(Wq, 256, idx, Pqh, Pql); return; }
    idx -= 65536;
    if (idx < 65536) { pack_one(Wk, 256, idx, Pkh, Pkl); return; }
    idx -= 65536;
    if (idx < 65536) { pack_one(Wv, 256, idx, Pv, nullptr); return; }
    idx -= 65536;
    if (idx < 32768) { pack_one(Whd, 256, idx, Phdh, Phdl); return; }
}

// ---------------------------------------------------------------------------
// Prep: small weight combinations (fp32)
// ---------------------------------------------------------------------------
__global__ void prep_small(const float* __restrict__ We, const float* __restrict__ Wgp,
                           const float* __restrict__ Wgd, const float* __restrict__ Wvg,
                           const float* __restrict__ Wgo,
                           float* Wg, float* W1, float* Wvg2, float* W2f)
{
    int idx = blockIdx.x * 256 + threadIdx.x;
    if (idx < 512) {
        int m = idx >> 5, n = idx & 31;
        float a = 0;
        for (int e = 0; e < 256; e++) a += We[m * 256 + e] * Wgp[e * 32 + n];
        Wg[idx] = 16.f * a; return;
    }
    idx -= 512;
    if (idx < 256) {
        int m = idx >> 4, j = idx & 15;
        float a = 0;
        for (int e = 0; e < 256; e++) a += We[m * 256 + e] * Wgd[e * 16 + j];
        W1[idx] = 16.f * a; return;
    }
    idx -= 256;
    if (idx < 4096) {
        int m = idx >> 8, c = idx & 255;
        float a = 0;
        for (int e = 0; e < 256; e++) a += We[m * 256 + e] * Wvg[e * 256 + c];
        Wvg2[idx] = 16.f * a; return;
    }
    idx -= 4096;
    if (idx < 4096) {
        int k = idx >> 4, j = idx & 15;
        float a = 0;
        for (int e = 0; e < 256; e++) a += Wgo[k * 256 + e] * Wgd[e * 16 + j];
        W2f[idx] = a;
    }
}

// W3p = pack(W_ng @ W_hdec); bias2 = b_ng@W_hdec + b_hdec
__global__ void prep_w3(const float* __restrict__ Wng, const float* __restrict__ Whd,
                        const float* __restrict__ bng, const float* __restrict__ bhd,
                        unsigned* W3p, float* bias2)
{
    int idx = blockIdx.x * 256 + threadIdx.x;
    if (idx < 32768) {
        int kp = idx >> 8, n = idx & 255;
        float a0 = 0, a1 = 0;
        for (int e = 0; e < 256; e++) {
            float w = Whd[e * 256 + n];
            a0 += Wng[(2 * kp) * 256 + e] * w;
            a1 += Wng[(2 * kp + 1) * 256 + e] * w;
        }
        __half2 h = __floats2half2_rn(a0, a1);
        W3p[idx] = *(unsigned*)&h;
        return;
    }
    idx -= 32768;
    if (idx < 256) {
        float a = bhd[idx];
        for (int k = 0; k < 256; k++) a += bng[k] * Whd[k * 256 + idx];
        bias2[idx] = a;
    }
}

// ---------------------------------------------------------------------------
// Fused g2p + gram
// ---------------------------------------------------------------------------
__global__ __launch_bounds__(128)
void g2p_gram(const float* __restrict__ equ, const float* __restrict__ Wg,
              __half* __restrict__ gram)
{
    __shared__ float wgs[512];
    __shared__ float es[48];
    __shared__ float g2s[96];
    int t = threadIdx.x;
    int node = blockIdx.x;
    #pragma unroll
    for (int i = 0; i < 4; i++) wgs[t + i * 128] = Wg[t + i * 128];
    if (t < 48) es[t] = equ[(size_t)node * 48 + t];
    __syncthreads();
    if (t < 96) {
        int i = t >> 5, a = t & 31;
        float acc = 0;
        #pragma unroll
        for (int k = 0; k < 16; k++) acc += es[i * 16 + k] * wgs[k * 32 + a];
        g2s[t] = acc;
    }
    __syncthreads();
    #pragma unroll
    for (int o = t; o < 1024; o += 128) {
        int a = o >> 5, b = o & 31;
        gram[(size_t)node * 1024 + o] = __float2half_rn(
            g2s[a] * g2s[b] + g2s[32 + a] * g2s[32 + b] + g2s[64 + a] * g2s[64 + b]);
    }
}

// vg = equ @ Wvg2 (K=16), written directly into paired attention layout.
__global__ __launch_bounds__(256)
void vg_small(const float* __restrict__ equ, const float* __restrict__ Wvg2,
              __half* __restrict__ vpH)
{
    __shared__ float ws[16 * 256];
    __shared__ float es[64 * 16];
    int tid = threadIdx.x;
    #pragma unroll
    for (int i = 0; i < 16; i++) ws[tid + i * 256] = Wvg2[tid + i * 256];
    int r0 = blockIdx.x * 64;
    #pragma unroll
    for (int i = 0; i < 4; i++) {
        int idx = tid + i * 256;
        es[idx] = equ[(size_t)r0 * 16 + idx];
    }
    __syncthreads();
    const int head = tid >> 5, d = tid & 31;
    for (int r = 0; r < 64; r++) {
        float acc = 0;
        #pragma unroll
        for (int k = 0; k < 16; k++) acc += es[r * 16 + k] * ws[k * 256 + tid];
        int gr = r0 + r;
        int node = gr / 3;
        int ch = gr - 3 * node;
        size_t w = ((size_t)(node >> 1) * 1024 + head * 128 + 32 + ch * 32 + d) * 2 + (node & 1);
        vpH[w] = __float2half_rn(acc);
    }
}

// h2 right half = 16h split hi/lo
__global__ void h2fill_kernel(const float* __restrict__ h,
                              __half* __restrict__ h2hi, __half* __restrict__ h2lo)
{
    int idx = blockIdx.x * blockDim.x + threadIdx.x;
    if (idx < NN * EE) {
        int r = idx >> 8, c = idx & 255;
        float v = 16.f * h[idx];
        __half hi = __float2half_rn(v);
        size_t o = (size_t)r * 512 + 256 + c;
        h2hi[o] = hi;
        h2lo[o] = __float2half_rn(v - __half2float(hi));
    }
}

// equ_out = equ@W1 + outg@W2f  (N=16 fused)
__global__ __launch_bounds__(256)
void equ_out_kernel(const float* __restrict__ equ, const __half* __restrict__ outg,
                    const float* __restrict__ W1, const float* __restrict__ W2,
                    float* __restrict__ out)
{
    __shared__ float w1s[256];
    __shared__ float w2s[4096];
    int tid = threadIdx.x;
    w1s[tid] = W1[tid];
    #pragma unroll
    for (int i = 0; i < 16; i++) w2s[tid + i * 256] = W2[tid + i * 256];
    __syncthreads();
    int lane = tid & 31, warp = tid >> 5;
    int row = blockIdx.x * 16 + warp * 2 + (lane >> 4);
    int j = lane & 15;
    float acc = 0;
    const float* er = equ + (size_t)row * 16;
    #pragma unroll
    for (int k = 0; k < 16; k++) acc += er[k] * w1s[k * 16 + j];
    const __half2* og = (const __half2*)(outg + (size_t)row * 256);
    #pragma unroll 8
    for (int kp = 0; kp < 128; kp++) {
        float2 v = __half22float2(og[kp]);
        acc += v.x * w2s[(2 * kp) * 16 + j] + v.y * w2s[(2 * kp + 1) * 16 + j];
    }
    out[(size_t)row * 16 + j] = acc;
}

// ---------------------------------------------------------------------------
// FP16 GEMM, 64x128 tile (8 warps, warp tile 32x32), 3-stage cp.async pipeline.
// ---------------------------------------------------------------------------
#define HA_STR 20
#define HB_STR 136
#define ASZ (64*HA_STR)
#define BSZ (16*HB_STR)

__device__ __forceinline__ void epi_store(float v0, float v1,
                                          float* outF, __half* outH, __half* outL,
                                          size_t off)
{
    if (outF) {
        *(float2*)&outF[off] = make_float2(v0, v1);
    } else if (outL) {
        __half h0 = __float2half_rn(v0), h1 = __float2half_rn(v1);
        __half2 hh = __halves2half2(h0, h1);
        ((__half2*)outH)[off >> 1] = hh;
        ((__half2*)outL)[off >> 1] =
            __floats2half2_rn(v0 - __half2float(h0), v1 - __half2float(h1));
    } else {
        ((__half2*)outH)[off >> 1] = __floats2half2_rn(v0, v1);
    }
}

#define STAGE_A_G(SRC, DST, K0) { \
    int row_ = tid >> 2, seg_ = tid & 3; \
    cp_async16(&(DST)[row_ * HA_STR + seg_ * 4], \
               &(SRC)[(size_t)(bm + row_) * lda + (K0) + seg_ * 8]); }
#define STAGE_B_G(SRC, DST, K0) { \
    _Pragma("unroll") \
    for (int i = 0; i < 2; i++) { \
        int idx = tid + i * 256; \
        int kp = idx >> 5, s = idx & 31; \
        cp_async16(&(DST)[kp * HB_STR + s * 4], \
                   &(SRC)[(size_t)(((K0) >> 1) + kp) * ldbw + bn + s * 4]); \
    } }

template<int NPASS, bool RELU>
__global__ __launch_bounds__(256)
void hgemm(const __half* __restrict__ A, const __half* __restrict__ Al, int lda,
           const unsigned* __restrict__ Bp, const unsigned* __restrict__ Bl, int ldbw,
           const float* __restrict__ bias,
           const float* __restrict__ Res, int ldres, float resScale, float alpha,
           float* __restrict__ outF, __half* __restrict__ outH, __half* __restrict__ outL,
           int ldc, int K)
{
    extern __shared__ unsigned smw[];
    unsigned* As  = smw;
    unsigned* Bs  = smw + 3 * ASZ;
    unsigned* Als = Bs + 3 * BSZ;
    unsigned* Bls = Als + 3 * ASZ;

    const int tid  = threadIdx.x;
    const int lane = tid & 31;
    const int warp = tid >> 5;
    const int bm   = blockIdx.y * 64;
    const int bn   = blockIdx.x * 128;
    const int wM   = (warp >> 2) * 32;
    const int wN   = (warp & 3) * 32;
    const int lr   = lane >> 2;
    const int lc   = lane & 3;

    float acc[2][4][4] = {};
    const int KT = K / 32;

    STAGE_A_G(A, As, 0);
    if (NPASS == 3) STAGE_A_G(Al, Als, 0);
    STAGE_B_G(Bp, Bs, 0);
    if (NPASS == 3) STAGE_B_G(Bl, Bls, 0);
    CP_COMMIT();
    STAGE_A_G(A, As + ASZ, 32);
    if (NPASS == 3) STAGE_A_G(Al, Als + ASZ, 32);
    STAGE_B_G(Bp, Bs + BSZ, 32);
    if (NPASS == 3) STAGE_B_G(Bl, Bls + BSZ, 32);
    CP_COMMIT();

    int scur = 0;
    for (int kt = 0; kt < KT; kt++) {
        if (kt + 2 < KT) {
            int s2 = scur + 2; if (s2 >= 3) s2 -= 3;
            int k0 = (kt + 2) * 32;
            STAGE_A_G(A, As + s2 * ASZ, k0);
            if (NPASS == 3) STAGE_A_G(Al, Als + s2 * ASZ, k0);
            STAGE_B_G(Bp, Bs + s2 * BSZ, k0);
            if (NPASS == 3) STAGE_B_G(Bl, Bls + s2 * BSZ, k0);
            CP_COMMIT();
            CP_WAIT(2);
        } else if (kt + 1 < KT) {
            CP_WAIT(1);
        } else {
            CP_WAIT(0);
        }
        __syncthreads();

        const unsigned* Ac  = As  + scur * ASZ;
        const unsigned* Bc  = Bs  + scur * BSZ;
        const unsigned* Alc = Als + scur * ASZ;
        const unsigned* Blc = Bls + scur * BSZ;

        #pragma unroll
        for (int ks = 0; ks < 2; ks++) {
            unsigned ah[2][4], al[2][4];
            #pragma unroll
            for (int mt = 0; mt < 2; mt++) {
                int rb = wM + mt * 16 + lr;
                int c  = ks * 8 + lc;
                ah[mt][0] = Ac[rb * HA_STR + c];
                ah[mt][1] = Ac[(rb + 8) * HA_STR + c];
                ah[mt][2] = Ac[rb * HA_STR + c + 4];
                ah[mt][3] = Ac[(rb + 8) * HA_STR + c + 4];
                if (NPASS == 3) {
                    al[mt][0] = Alc[rb * HA_STR + c];
                    al[mt][1] = Alc[(rb + 8) * HA_STR + c];
                    al[mt][2] = Alc[rb * HA_STR + c + 4];
                    al[mt][3] = Alc[(rb + 8) * HA_STR + c + 4];
                }
            }
            unsigned bh[4][2], bl[4][2];
            #pragma unroll
            for (int nt = 0; nt < 4; nt++) {
                int n  = wN + nt * 8 + lr;
                int kp = ks * 8 + lc;
                bh[nt][0] = Bc[kp * HB_STR + n];
                bh[nt][1] = Bc[(kp + 4) * HB_STR + n];
                if (NPASS == 3) {
                    bl[nt][0] = Blc[kp * HB_STR + n];
                    bl[nt][1] = Blc[(kp + 4) * HB_STR + n];
                }
            }
            #pragma unroll
            for (int mt = 0; mt < 2; mt++)
                #pragma unroll
                for (int nt = 0; nt < 4; nt++) {
                    mma_f16(acc[mt][nt], ah[mt][0], ah[mt][1], ah[mt][2], ah[mt][3],
                            bh[nt][0], bh[nt][1]);
                    if (NPASS == 3) {
                        mma_f16(acc[mt][nt], ah[mt][0], ah[mt][1], ah[mt][2], ah[mt][3],
                                bl[nt][0], bl[nt][1]);
                        mma_f16(acc[mt][nt], al[mt][0], al[mt][1], al[mt][2], al[mt][3],
                                bh[nt][0], bh[nt][1]);
                    }
                }
        }
        __syncthreads();
        scur = scur + 1; if (scur == 3) scur = 0;
    }

    #pragma unroll
    for (int mt = 0; mt < 2; mt++) {
        #pragma unroll
        for (int nt = 0; nt < 4; nt++) {
            int col = bn + wN + nt * 8 + 2 * lc;
            #pragma unroll
            for (int half = 0; half < 2; half++) {
                int r = bm + wM + mt * 16 + lr + half * 8;
                float v0 = acc[mt][nt][half * 2 + 0];
                float v1 = acc[mt][nt][half * 2 + 1];
                if (bias) { v0 += bias[col]; v1 += bias[col + 1]; }
                v0 *= alpha; v1 *= alpha;
                if (Res) {
                    v0 = fmaf(resScale, Res[(size_t)r * ldres + col], v0);
                    v1 = fmaf(resScale, Res[(size_t)r * ldres + col + 1], v1);
                }
                if (RELU) { v0 = fmaxf(v0, 0.f); v1 = fmaxf(v1, 0.f); }
                epi_store(v0, v1, outF, outH, outL, (size_t)r * ldc + col);
            }
        }
    }
}

// ---------------------------------------------------------------------------
// Fused QKV (q/k x3 split-out; v x1 direct to vpair layout). 64x128 tiles.
// ---------------------------------------------------------------------------
__global__ __launch_bounds__(256)
void qkv_hgemm(const __half* __restrict__ A, const __half* __restrict__ Al,
               const unsigned* __restrict__ Pqh, const unsigned* __restrict__ Pql,
               const unsigned* __restrict__ Pkh, const unsigned* __restrict__ Pkl,
               const unsigned* __restrict__ Pv,
               const float* __restrict__ bq, const float* __restrict__ bk,
               const float* __restrict__ bv,
               __half* qh, __half* ql, __half* kh, __half* kl,
               __half* __restrict__ vpH,
               float qalpha)
{
    extern __shared__ unsigned smw[];
    unsigned* As  = smw;
    unsigned* Bs  = smw + 3 * ASZ;
    unsigned* Als = Bs + 3 * BSZ;
    unsigned* Bls = Als + 3 * ASZ;

    const int seg = blockIdx.z;
    const bool x3 = (seg < 2);
    const unsigned* Bp = (seg == 0) ? Pqh : (seg == 1) ? Pkh : Pv;
    const unsigned* Bl = (seg == 0) ? Pql : (seg == 1) ? Pkl : nullptr;
    const float* bias  = (seg == 0) ? bq : (seg == 1) ? bk : bv;
    __half* outH = (seg == 0) ? qh : kh;
    __half* outL = (seg == 0) ? ql : kl;
    const float alpha = (seg == 0) ? qalpha : 1.f;
    const int lda = 512, ldbw = 256, ldc = 256, K = 512;

    const int tid  = threadIdx.x;
    const int lane = tid & 31;
    const int warp = tid >> 5;
    const int bm   = blockIdx.y * 64;
    const int bn   = blockIdx.x * 128;
    const int wM   = (warp >> 2) * 32;
    const int wN   = (warp & 3) * 32;
    const int lr   = lane >> 2;
    const int lc   = lane & 3;

    float acc[2][4][4] = {};
    const int KT = K / 32;

    STAGE_A_G(A, As, 0);
    if (x3) STAGE_A_G(Al, Als, 0);
    STAGE_B_G(Bp, Bs, 0);
    if (x3) STAGE_B_G(Bl, Bls, 0);
    CP_COMMIT();
    STAGE_A_G(A, As + ASZ, 32);
    if (x3) STAGE_A_G(Al, Als + ASZ, 32);
    STAGE_B_G(Bp, Bs + BSZ, 32);
    if (x3) STAGE_B_G(Bl, Bls + BSZ, 32);
    CP_COMMIT();

    int scur = 0;
    for (int kt = 0; kt < KT; kt++) {
        if (kt + 2 < KT) {
            int s2 = scur + 2; if (s2 >= 3) s2 -= 3;
            int k0 = (kt + 2) * 32;
            STAGE_A_G(A, As + s2 * ASZ, k0);
            if (x3) STAGE_A_G(Al, Als + s2 * ASZ, k0);
            STAGE_B_G(Bp, Bs + s2 * BSZ, k0);
            if (x3) STAGE_B_G(Bl, Bls + s2 * BSZ, k0);
            CP_COMMIT();
            CP_WAIT(2);
        } else if (kt + 1 < KT) {
            CP_WAIT(1);
        } else {
            CP_WAIT(0);
        }
        __syncthreads();

        const unsigned* Ac  = As  + scur * ASZ;
        const unsigned* Bc  = Bs  + scur * BSZ;
        const unsigned* Alc = Als + scur * ASZ;
        const unsigned* Blc = Bls + scur * BSZ;

        #pragma unroll
        for (int ks = 0; ks < 2; ks++) {
            unsigned ah[2][4], al[2][4];
            #pragma unroll
            for (int mt = 0; mt < 2; mt++) {
                int rb = wM + mt * 16 + lr;
                int c  = ks * 8 + lc;
                ah[mt][0] = Ac[rb * HA_STR + c];
                ah[mt][1] = Ac[(rb + 8) * HA_STR + c];
                ah[mt][2] = Ac[rb * HA_STR + c + 4];
                ah[mt][3] = Ac[(rb + 8) * HA_STR + c + 4];
                if (x3) {
                    al[mt][0] = Alc[rb * HA_STR + c];
                    al[mt][1] = Alc[(rb + 8) * HA_STR + c];
                    al[mt][2] = Alc[rb * HA_STR + c + 4];
                    al[mt][3] = Alc[(rb + 8) * HA_STR + c + 4];
                }
            }
            unsigned bh[4][2], bl[4][2];
            #pragma unroll
            for (int nt = 0; nt < 4; nt++) {
                int n  = wN + nt * 8 + lr;
                int kp = ks * 8 + lc;
                bh[nt][0] = Bc[kp * HB_STR + n];
                bh[nt][1] = Bc[(kp + 4) * HB_STR + n];
                if (x3) {
                    bl[nt][0] = Blc[kp * HB_STR + n];
                    bl[nt][1] = Blc[(kp + 4) * HB_STR + n];
                }
            }
            #pragma unroll
            for (int mt = 0; mt < 2; mt++)
                #pragma unroll
                for (int nt = 0; nt < 4; nt++) {
                    mma_f16(acc[mt][nt], ah[mt][0], ah[mt][1], ah[mt][2], ah[mt][3],
                            bh[nt][0], bh[nt][1]);
                    if (x3) {
                        mma_f16(acc[mt][nt], ah[mt][0], ah[mt][1], ah[mt][2], ah[mt][3],
                                bl[nt][0], bl[nt][1]);
                        mma_f16(acc[mt][nt], al[mt][0], al[mt][1], al[mt][2], al[mt][3],
                                bh[nt][0], bh[nt][1]);
                    }
                }
        }
        __syncthreads();
        scur = scur + 1; if (scur == 3) scur = 0;
    }

    #pragma unroll
    for (int mt = 0; mt < 2; mt++) {
        #pragma unroll
        for (int nt = 0; nt < 4; nt++) {
            int col = bn + wN + nt * 8 + 2 * lc;
            #pragma unroll
            for (int half = 0; half < 2; half++) {
                int r = bm + wM + mt * 16 + lr + half * 8;
                float v0 = (acc[mt][nt][half * 2 + 0] + bias[col]) * alpha;
                float v1 = (acc[mt][nt][half * 2 + 1] + bias[col + 1]) * alpha;
                if (seg == 2) {
                    int head = col >> 5, d = col & 31;
                    size_t w = ((size_t)(r >> 1) * 1024 + head * 128 + d) * 2 + (r & 1);
                    vpH[w]     = __float2half_rn(v0);
                    vpH[w + 2] = __float2half_rn(v1);
                } else {
                    epi_store(v0, v1, nullptr, outH, outL, (size_t)r * ldc + col);
                }
            }
        }
    }
}

// ---------------------------------------------------------------------------
// Flash attention v10: 4 warps x 32 q-rows (B-frags feed 2 MMAs each ->
// smem crossbar traffic halves), triple-buffered K/V rings, one sync/tile,
// exp2 softmax, warp-voted rescale skip.
// ---------------------------------------------------------------------------
#define AQ 128
#define AK 64
#define QP 20
#define VPSTR 136
#define KBUF 1280
#define VBUF 4352

#define ATTN_WORDS (2560*2 + 3*KBUF*2 + 3*VBUF)   // 25856
#define ATTN_SMEM  (ATTN_WORDS * 4)               // 103424

__global__ __launch_bounds__(128, 2)
void attn_kernel(const unsigned* __restrict__ qhiW, const unsigned* __restrict__ qloW,
                 const unsigned* __restrict__ khiW, const unsigned* __restrict__ kloW,
                 const unsigned* __restrict__ vpW,
                 __half* __restrict__ outv, __half* __restrict__ outg)
{
    extern __shared__ unsigned smw[];
    unsigned* Qhi  = smw;                    // [128][QP]
    unsigned* Qlo  = Qhi + 2560;
    unsigned* Khi3 = Qlo + 2560;             // 3 x [64][QP]
    unsigned* Klo3 = Khi3 + 3 * KBUF;
    unsigned* Vp3  = Klo3 + 3 * KBUF;        // 3 x [32][VPSTR]

    const int head = blockIdx.y;
    const int qb   = blockIdx.x * AQ;
    const int tid  = threadIdx.x;            // 128 threads
    const int lane = tid & 31;
    const int warp = tid >> 5;               // 0..3
    const int hofw = head * 16;
    const int hof  = head * DD;
    const int lr   = lane >> 2;
    const int lc   = lane & 3;
    const int wRow = warp * 32;

    // prologue: V(0) group, then K(0)+Q group  (128-thread staging)
    {
        #pragma unroll
        for (int i = 0; i < 8; i++) {
            int idx = tid + i * 128;
            int pr = idx >> 5, s = idx & 31;
            cp_async16(&Vp3[pr * VPSTR + s * 4],
                       &vpW[(size_t)pr * 1024 + head * 128 + s * 4]);
        }
        CP_COMMIT();
    }
    {
        #pragma unroll
        for (int i = 0; i < 2; i++) {
            int idx = tid + i * 128;
            int key = idx >> 2, seg = idx & 3;
            cp_async16(&Khi3[key * QP + seg * 4], &khiW[(size_t)key * 128 + hofw + seg * 4]);
            cp_async16(&Klo3[key * QP + seg * 4], &kloW[(size_t)key * 128 + hofw + seg * 4]);
        }
        #pragma unroll
        for (int i = 0; i < 4; i++) {
            int idx = tid + i * 128;
            int row = idx >> 2, sg = idx & 3;
            cp_async16(&Qhi[row * QP + sg * 4], &qhiW[(size_t)(qb + row) * 128 + hofw + sg * 4]);
            cp_async16(&Qlo[row * QP + sg * 4], &qloW[(size_t)(qb + row) * 128 + hofw + sg * 4]);
        }
        CP_COMMIT();
    }

    float O[2][16][4] = {};
    float m_[2][2], l_[2][2];
    #pragma unroll
    for (int mt = 0; mt < 2; mt++) {
        m_[mt][0] = -1e30f; m_[mt][1] = -1e30f;
        l_[mt][0] = 0.f;    l_[mt][1] = 0.f;
    }

    int bcur = 0;
    for (int t = 0; t < NN / AK; t++) {
        const bool hasNext = (t + 1 < NN / AK);
        int bnext = bcur + 1; if (bnext == 3) bnext = 0;

        if (hasNext) {
            const int kb1 = (t + 1) * AK;
            unsigned* Vd = Vp3 + bnext * VBUF;
            const int p0 = kb1 >> 1;
            #pragma unroll
            for (int i = 0; i < 8; i++) {
                int idx = tid + i * 128;
                int pr = idx >> 5, s = idx & 31;
                cp_async16(&Vd[pr * VPSTR + s * 4],
                           &vpW[((size_t)(p0 + pr)) * 1024 + head * 128 + s * 4]);
            }
            CP_COMMIT();
            unsigned* Kdh = Khi3 + bnext * KBUF;
            unsigned* Kdl = Klo3 + bnext * KBUF;
            #pragma unroll
            for (int i = 0; i < 2; i++) {
                int idx = tid + i * 128;
                int key = idx >> 2, seg = idx & 3;
                cp_async16(&Kdh[key * QP + seg * 4],
                           &khiW[(size_t)(kb1 + key) * 128 + hofw + seg * 4]);
                cp_async16(&Kdl[key * QP + seg * 4],
                           &kloW[(size_t)(kb1 + key) * 128 + hofw + seg * 4]);
            }
            CP_COMMIT();
            CP_WAIT(2);
        } else {
            CP_WAIT(0);
        }
        __syncthreads();

        const unsigned* Kh = Khi3 + bcur * KBUF;
        const unsigned* Kl = Klo3 + bcur * KBUF;
        const unsigned* Vp = Vp3 + bcur * VBUF;

        #pragma unroll
        for (int half = 0; half < 2; half++) {
            // ---- S = Q K^T (fp16x3), warp covers 32 q rows ----
            float s[2][4][4] = {};
            #pragma unroll
            for (int ks = 0; ks < 2; ks++) {
                int c = ks * 8 + lc;
                unsigned ah[2][4], al[2][4];
                #pragma unroll
                for (int mt = 0; mt < 2; mt++) {
                    int rb = wRow + mt * 16 + lr;
                    ah[mt][0] = Qhi[rb * QP + c];
                    ah[mt][1] = Qhi[(rb + 8) * QP + c];
                    ah[mt][2] = Qhi[rb * QP + c + 4];
                    ah[mt][3] = Qhi[(rb + 8) * QP + c + 4];
                    al[mt][0] = Qlo[rb * QP + c];
                    al[mt][1] = Qlo[(rb + 8) * QP + c];
                    al[mt][2] = Qlo[rb * QP + c + 4];
                    al[mt][3] = Qlo[(rb + 8) * QP + c + 4];
                }
                #pragma unroll
                for (int nt = 0; nt < 4; nt++) {
                    int key = half * 32 + nt * 8 + lr;
                    unsigned bh0 = Kh[key * QP + c];
                    unsigned bh1 = Kh[key * QP + c + 4];
                    unsigned bl0 = Kl[key * QP + c];
                    unsigned bl1 = Kl[key * QP + c + 4];
                    #pragma unroll
                    for (int mt = 0; mt < 2; mt++) {
                        mma_f16(s[mt][nt], ah[mt][0], ah[mt][1], ah[mt][2], ah[mt][3], bh0, bh1);
                        mma_f16(s[mt][nt], ah[mt][0], ah[mt][1], ah[mt][2], ah[mt][3], bl0, bl1);
                        mma_f16(s[mt][nt], al[mt][0], al[mt][1], al[mt][2], al[mt][3], bh0, bh1);
                    }
                }
            }

            // ---- online softmax per mt (base 2) ----
            unsigned pa[2][2][4];
            float alpha[2][2];
            #pragma unroll
            for (int mt = 0; mt < 2; mt++) {
                float mx0 = m_[mt][0], mx1 = m_[mt][1];
                #pragma unroll
                for (int nt = 0; nt < 4; nt++) {
                    mx0 = fmaxf(mx0, fmaxf(s[mt][nt][0], s[mt][nt][1]));
                    mx1 = fmaxf(mx1, fmaxf(s[mt][nt][2], s[mt][nt][3]));
                }
                mx0 = fmaxf(mx0, __shfl_xor_sync(0xffffffff, mx0, 1));
                mx0 = fmaxf(mx0, __shfl_xor_sync(0xffffffff, mx0, 2));
                mx1 = fmaxf(mx1, __shfl_xor_sync(0xffffffff, mx1, 1));
                mx1 = fmaxf(mx1, __shfl_xor_sync(0xffffffff, mx1, 2));

                float a0 = exp2f(m_[mt][0] - mx0);
                float a1 = exp2f(m_[mt][1] - mx1);
                float sum0 = 0.f, sum1 = 0.f;
                #pragma unroll
                for (int nt = 0; nt < 4; nt++) {
                    s[mt][nt][0] = exp2f(s[mt][nt][0] - mx0);
                    s[mt][nt][1] = exp2f(s[mt][nt][1] - mx0);
                    s[mt][nt][2] = exp2f(s[mt][nt][2] - mx1);
                    s[mt][nt][3] = exp2f(s[mt][nt][3] - mx1);
                    sum0 += s[mt][nt][0] + s[mt][nt][1];
                    sum1 += s[mt][nt][2] + s[mt][nt][3];
                }
                sum0 += __shfl_xor_sync(0xffffffff, sum0, 1);
                sum0 += __shfl_xor_sync(0xffffffff, sum0, 2);
                sum1 += __shfl_xor_sync(0xffffffff, sum1, 1);
                sum1 += __shfl_xor_sync(0xffffffff, sum1, 2);
                l_[mt][0] = l_[mt][0] * a0 + sum0;  m_[mt][0] = mx0;
                l_[mt][1] = l_[mt][1] * a1 + sum1;  m_[mt][1] = mx1;
                alpha[mt][0] = a0; alpha[mt][1] = a1;

                #pragma unroll
                for (int t16 = 0; t16 < 2; t16++) {
                    pa[mt][t16][0] = h2pack(s[mt][2 * t16][0],     s[mt][2 * t16][1]);
                    pa[mt][t16][1] = h2pack(s[mt][2 * t16][2],     s[mt][2 * t16][3]);
                    pa[mt][t16][2] = h2pack(s[mt][2 * t16 + 1][0], s[mt][2 * t16 + 1][1]);
                    pa[mt][t16][3] = h2pack(s[mt][2 * t16 + 1][2], s[mt][2 * t16 + 1][3]);
                }
            }

            // O-rescale only if any lane's max advanced (exact skip)
            bool noresc = (alpha[0][0] == 1.f) && (alpha[0][1] == 1.f) &&
                          (alpha[1][0] == 1.f) && (alpha[1][1] == 1.f);
            if (!__all_sync(0xffffffff, noresc)) {
                #pragma unroll
                for (int mt = 0; mt < 2; mt++)
                    #pragma unroll
                    for (int nt = 0; nt < 16; nt++) {
                        O[mt][nt][0] *= alpha[mt][0]; O[mt][nt][1] *= alpha[mt][0];
                        O[mt][nt][2] *= alpha[mt][1]; O[mt][nt][3] *= alpha[mt][1];
                    }
            }

            // ---- PV: each B-frag load feeds both mt ----
            #pragma unroll
            for (int t16 = 0; t16 < 2; t16++) {
                int kpb = half * 16 + t16 * 8;
                #pragma unroll
                for (int nt = 0; nt < 16; nt++) {
                    int n = nt * 8 + lr;
                    unsigned b0 = Vp[(kpb + lc) * VPSTR + n];
                    unsigned b1 = Vp[(kpb + 4 + lc) * VPSTR + n];
                    mma_f16(O[0][nt], pa[0][t16][0], pa[0][t16][1], pa[0][t16][2], pa[0][t16][3], b0, b1);
                    mma_f16(O[1][nt], pa[1][t16][0], pa[1][t16][1], pa[1][t16][2], pa[1][t16][3], b0, b1);
                }
            }
        }
        bcur = bnext;
    }

    // epilogue
    unsigned* outvW = (unsigned*)outv;
    unsigned* outgW = (unsigned*)outg;
    #pragma unroll
    for (int mt = 0; mt < 2; mt++) {
        float linv0 = 1.f / l_[mt][0];
        float linv1 = 1.f / l_[mt][1];
        int r0 = qb + wRow + mt * 16 + lr;
        int r1 = r0 + 8;
        #pragma unroll
        for (int nt = 0; nt < 16; nt++) {
            int c = nt * 8 + 2 * lc;
            unsigned w0 = h2pack(O[mt][nt][0] * linv0, O[mt][nt][1] * linv0);
            unsigned w1 = h2pack(O[mt][nt][2] * linv1, O[mt][nt][3] * linv1);
            if (c < 32) {
                outvW[(size_t)r0 * 128 + (hof + c) / 2] = w0;
                outvW[(size_t)r1 * 128 + (hof + c) / 2] = w1;
            } else {
                int ch = (c - 32) >> 5;
                int d  = (c - 32) & 31;
                outgW[((size_t)r0 * 3 + ch) * 128 + (hof + d) / 2] = w0;
                outgW[((size_t)r1 * 3 + ch) * 128 + (hof + d) / 2] = w1;
            }
        }
    }
}

// ---------------------------------------------------------------------------
// Host orchestration (multi-stream fork/join, capture-safe)
// ---------------------------------------------------------------------------
extern "C" void kernel_launch(void* const* d_in, const int* in_sizes, int n_in,
                              void* d_out, int out_size)
{
    const float* equ    = (const float*)d_in[0];
    const float* h      = (const float*)d_in[1];
    const float* W_equ  = (const float*)d_in[4];
    const float* W_gproj= (const float*)d_in[5];
    const float* W_vg   = (const float*)d_in[6];
    const float* W_g1   = (const float*)d_in[7];
    const float* b_g1   = (const float*)d_in[8];
    const float* W_g2   = (const float*)d_in[9];
    const float* b_g2   = (const float*)d_in[10];
    const float* W_q    = (const float*)d_in[11];
    const float* b_q    = (const float*)d_in[12];
    const float* W_k    = (const float*)d_in[13];
    const float* b_k    = (const float*)d_in[14];
    const float* W_v    = (const float*)d_in[15];
    const float* b_v    = (const float*)d_in[16];
    const float* W_ng   = (const float*)d_in[17];
    const float* b_ng   = (const float*)d_in[18];
    const float* W_gout = (const float*)d_in[19];
    const float* W_gdec = (const float*)d_in[20];
    const float* W_hdec = (const float*)d_in[21];
    const float* b_hdec = (const float*)d_in[22];

    float* out = (float*)d_out;

    static cudaStream_t s1 = nullptr, s2 = nullptr;
    static cudaEvent_t evRoot, evPrep, evPack, evH2, evVg, evAttn, evS1, evHout;
    if (!s1) {
        cudaStreamCreateWithFlags(&s1, cudaStreamNonBlocking);
        cudaStreamCreateWithFlags(&s2, cudaStreamNonBlocking);
        cudaEventCreateWithFlags(&evRoot, cudaEventDisableTiming);
        cudaEventCreateWithFlags(&evPrep, cudaEventDisableTiming);
        cudaEventCreateWithFlags(&evPack, cudaEventDisableTiming);
        cudaEventCreateWithFlags(&evH2, cudaEventDisableTiming);
        cudaEventCreateWithFlags(&evVg, cudaEventDisableTiming);
        cudaEventCreateWithFlags(&evAttn, cudaEventDisableTiming);
        cudaEventCreateWithFlags(&evS1, cudaEventDisableTiming);
        cudaEventCreateWithFlags(&evHout, cudaEventDisableTiming);
    }

    float* S = nullptr;
    cudaGetSymbolAddress((void**)&S, scratch);

    const int SM1 = (3 * ASZ + 3 * BSZ) * 4;        // 41472
    const int SM3 = SM1 * 2;                        // 82944
    cudaFuncSetAttribute(hgemm<1, true>,  cudaFuncAttributeMaxDynamicSharedMemorySize, SM1);
    cudaFuncSetAttribute(hgemm<1, false>, cudaFuncAttributeMaxDynamicSharedMemorySize, SM1);
    cudaFuncSetAttribute(hgemm<3, false>, cudaFuncAttributeMaxDynamicSharedMemorySize, SM3);
    cudaFuncSetAttribute(qkv_hgemm, cudaFuncAttributeMaxDynamicSharedMemorySize, SM3);
    cudaFuncSetAttribute(attn_kernel, cudaFuncAttributeMaxDynamicSharedMemorySize, ATTN_SMEM);

    __half* gram_h = (__half*)(S + OFF_GRAM);
    __half* hid_h  = (__half*)(S + OFF_HID);
    __half* h2hi   = (__half*)(S + OFF_H2HI);
    __half* h2lo   = (__half*)(S + OFF_H2LO);
    __half* qhi    = (__half*)(S + OFF_QHI);
    __half* qlo    = (__half*)(S + OFF_QLO);
    __half* khi    = (__half*)(S + OFF_KHI);
    __half* klo    = (__half*)(S + OFF_KLO);
    unsigned* vpair= (unsigned*)(S + OFF_VPAIR);
    __half* outv_h = (__half*)(S + OFF_OUTV);
    __half* outg_h = (__half*)(S + OFF_OUTG);
    float*  hpre   = S + OFF_HPRE;
    unsigned* Pg1  = (unsigned*)(S + OFF_PG1);
    unsigned* Pg2  = (unsigned*)(S + OFF_PG2);
    unsigned* Pqh  = (unsigned*)(S + OFF_PQH);
    unsigned* Pql  = (unsigned*)(S + OFF_PQL);
    unsigned* Pkh  = (unsigned*)(S + OFF_PKH);
    unsigned* Pkl  = (unsigned*)(S + OFF_PKL);
    unsigned* Pv   = (unsigned*)(S + OFF_PV);
    unsigned* Phdh = (unsigned*)(S + OFF_PHDH);
    unsigned* Phdl = (unsigned*)(S + OFF_PHDL);
    unsigned* W3p  = (unsigned*)(S + OFF_W3P);
    float* Wg      = S + OFF_WG;
    float* W1      = S + OFF_W1;
    float* Wvg2    = S + OFF_WVG2;
    float* W2f     = S + OFF_W2F;
    float* bias2   = S + OFF_BIAS2;

    const float qalpha = 0.17677669529663687f * 1.4426950408889634f;

    // ---- fork ----
    cudaEventRecord(evRoot, 0);
    cudaStreamWaitEvent(s1, evRoot, 0);
    cudaStreamWaitEvent(s2, evRoot, 0);

    // s2: h2fill early (only needs h)
    h2fill_kernel<<<(NN * EE + 255) / 256, 256, 0, s2>>>(h, h2hi, h2lo);
    cudaEventRecord(evH2, s2);

    // s1: weight packing + W3/bias2 + hpre
    pack_weights<<<2176, 256, 0, s1>>>(W_g1, W_g2, W_q, W_k, W_v, W_hdec,
                                       Pg1, Pg2, Pqh, Pql, Pkh, Pkl, Pv, Phdh, Phdl);
    cudaEventRecord(evPack, s1);
    prep_w3<<<129, 256, 0, s1>>>(W_ng, W_hdec, b_ng, b_hdec, W3p, bias2);
    cudaStreamWaitEvent(s1, evH2, 0);
    hgemm<3, false><<<dim3(2, 64), 256, SM3, s1>>>(h2hi + 256, h2lo + 256, 512,
                                                   Phdh, Phdl, 256,
                                                   bias2, nullptr, 0, 0.f, 1.f,
                                                   hpre, nullptr, nullptr, 256, 256);
    cudaEventRecord(evS1, s1);

    // main: prep combos
    prep_small<<<35, 256>>>(W_equ, W_gproj, W_gdec, W_vg, W_gout, Wg, W1, Wvg2, W2f);
    cudaEventRecord(evPrep, 0);

    // s2: vg -> vpair direct
    cudaStreamWaitEvent(s2, evPrep, 0);
    vg_small<<<192, 256, 0, s2>>>(equ, Wvg2, (__half*)vpair);
    cudaEventRecord(evVg, s2);

    // main: gram -> MLP -> qkv -> attention
    g2p_gram<<<NN, 128>>>(equ, Wg, gram_h);
    cudaStreamWaitEvent(0, evPack, 0);
    hgemm<1, true><<<dim3(4, 64), 256, SM1>>>(gram_h, nullptr, 1024, Pg1, nullptr, 512,
                                              b_g1, nullptr, 0, 0.f, 1.f,
                                              nullptr, hid_h, nullptr, 512, 1024);
    hgemm<1, false><<<dim3(2, 64), 256, SM1>>>(hid_h, nullptr, 512, Pg2, nullptr, 256,
                                               b_g2, nullptr, 0, 0.f, 1.f,
                                               nullptr, h2hi, h2lo, 512, 512);
    cudaStreamWaitEvent(0, evH2, 0);
    qkv_hgemm<<<dim3(2, 64, 3), 256, SM3>>>(h2hi, h2lo, Pqh, Pql, Pkh, Pkl, Pv,
                                            b_q, b_k, b_v, qhi, qlo, khi, klo,
                                            (__half*)vpair, qalpha);
    cudaStreamWaitEvent(0, evVg, 0);
    attn_kernel<<<dim3(NN / AQ, HH), 128, ATTN_SMEM>>>(
        (const unsigned*)qhi, (const unsigned*)qlo,
        (const unsigned*)khi, (const unsigned*)klo,
        vpair, outv_h, outg_h);
    cudaEventRecord(evAttn, 0);

    // s2: h_out = outv@W3 + hpre
    cudaStreamWaitEvent(s2, evAttn, 0);
    cudaStreamWaitEvent(s2, evS1, 0);
    hgemm<1, false><<<dim3(2, 64), 256, SM1, s2>>>(outv_h, nullptr, 256, W3p, nullptr, 256,
                                                   nullptr, hpre, 256, 1.f, 1.f,
                                                   out + (size_t)ROWS * MMDIM,
                                                   nullptr, nullptr, 256, 256);
    cudaEventRecord(evHout, s2);

    // main: equ_out = equ@W1 + outg@W2f
    equ_out_kernel<<<768, 256>>>(equ, outg_h, W1, W2f, out);

    // ---- join ----
    cudaStreamWaitEvent(0, evHout, 0);
}